// round 1
// baseline (speedup 1.0000x reference)
#include <cuda_runtime.h>
#include <math.h>

// Problem constants
#define BB    256     // batch
#define SS    128     // seq len
#define IN_D  192
#define MLP_O 256
#define HH    1024
#define AA    64
#define LSTM_IN 320   // MLP_O + A
#define G4    4096    // 4*H
#define NCTA  128     // persistent LSTM grid

// ---------------- device scratch (no allocs allowed) ----------------
__device__ float g_WcT[IN_D * MLP_O];          // [k][o] collapsed MLP weight, transposed
__device__ float g_bc[MLP_O];                  // collapsed MLP bias
__device__ float g_bias[G4];                   // b_ih + b_hh
__device__ float g_mlp[SS * BB * MLP_O];       // [s][b][o]  32 MB
__device__ float g_inp[BB * LSTM_IN];          // [b][320] = [mlp_t | o_prev]
__device__ float g_h[2][BB * HH];              // double-buffered hidden
__device__ float g_c[BB * HH];                 // cell (exclusively owned per j-slice)
__device__ unsigned g_cnt = 0;
__device__ unsigned g_gen = 0;

// ---------------- grid barrier (replay-safe) ----------------
__device__ __forceinline__ void grid_barrier(unsigned &gen)
{
    __syncthreads();
    if (threadIdx.x == 0) {
        __threadfence();
        unsigned ticket = atomicAdd(&g_cnt, 1u);
        if (ticket == NCTA - 1u) {
            g_cnt = 0u;
            __threadfence();
            atomicAdd(&g_gen, 1u);
        } else {
            while (*((volatile unsigned *)&g_gen) == gen) { }
            __threadfence();
        }
    }
    gen += 1u;
    __syncthreads();
}

// ---------------- kernel 0: biases ----------------
__global__ void bias_kernel(const float* __restrict__ W2, const float* __restrict__ b1,
                            const float* __restrict__ b2, const float* __restrict__ bih,
                            const float* __restrict__ bhh)
{
    int tid = threadIdx.x;
    for (int n = tid; n < G4; n += 256) g_bias[n] = bih[n] + bhh[n];
    // bc[o] = sum_h W2[o][h]*b1[h] + b2[o]
    const float* w2r = W2 + tid * 1024;
    float acc = b2[tid];
    #pragma unroll 4
    for (int h = 0; h < 1024; h += 4) {
        float4 w = *(const float4*)(w2r + h);
        acc = fmaf(w.x, b1[h], acc);
        acc = fmaf(w.y, b1[h+1], acc);
        acc = fmaf(w.z, b1[h+2], acc);
        acc = fmaf(w.w, b1[h+3], acc);
    }
    g_bc[tid] = acc;
}

// ---------------- kernel 1: collapse W2@W1 -> WcT[k][o] ----------------
__global__ void collapse_kernel(const float* __restrict__ W1, const float* __restrict__ W2)
{
    __shared__ float w1k[1024];
    int k = blockIdx.x;              // 0..191 (input feature)
    for (int h = threadIdx.x; h < 1024; h += 256) w1k[h] = W1[h * IN_D + k];
    __syncthreads();
    int o = threadIdx.x;             // 0..255
    const float* w2r = W2 + o * 1024;
    float acc = 0.f;
    #pragma unroll 4
    for (int h = 0; h < 1024; h += 4) {
        float4 w = *(const float4*)(w2r + h);
        acc = fmaf(w.x, w1k[h],   acc);
        acc = fmaf(w.y, w1k[h+1], acc);
        acc = fmaf(w.z, w1k[h+2], acc);
        acc = fmaf(w.w, w1k[h+3], acc);
    }
    g_WcT[k * MLP_O + o] = acc;
}

// ---------------- kernel 2: mlp[s][b][o] = relu(x @ Wc^T + bc) ----------------
#define MLP_TILE 16
__global__ void mlp_kernel(const float* __restrict__ observe,
                           const float* __restrict__ obstacle,
                           const float* __restrict__ mask)
{
    __shared__ float xs[MLP_TILE * IN_D];
    int tid = threadIdx.x;
    int p0 = blockIdx.x * MLP_TILE;         // flat (b*S+s) base
    // build masked+flattened inputs for 16 tokens
    for (int idx = tid; idx < MLP_TILE * IN_D; idx += 256) {
        int i = idx / IN_D, k = idx - i * IN_D;
        int p = p0 + i;
        float v;
        if (k < 64) {
            v = observe[p * 64 + k];
        } else {
            int kk = k - 64;                // 0..127
            int n = kk >> 4;                // obstacle index
            v = obstacle[p * 128 + kk] * mask[p * 8 + n];
        }
        xs[i * IN_D + k] = v;
    }
    __syncthreads();

    float acc[MLP_TILE];
    #pragma unroll
    for (int i = 0; i < MLP_TILE; i++) acc[i] = 0.f;
    #pragma unroll 4
    for (int k = 0; k < IN_D; k++) {
        float w = g_WcT[k * MLP_O + tid];
        #pragma unroll
        for (int i = 0; i < MLP_TILE; i++)
            acc[i] = fmaf(xs[i * IN_D + k], w, acc[i]);
    }
    float bcv = g_bc[tid];
    #pragma unroll
    for (int i = 0; i < MLP_TILE; i++) {
        int p = p0 + i;
        int b = p >> 7, s = p & 127;
        g_mlp[(s * BB + b) * MLP_O + tid] = fmaxf(acc[i] + bcv, 0.f);
    }
}

// ---------------- persistent LSTM kernel ----------------
struct LstmSmem {
    union {
        struct { float A[16][256]; float B[16][32]; } ld;
        float sg[32][257];
        float red[2][4][64];
    } u;
};

template<int LDA>
__device__ __forceinline__ void gemm_seg(
    float (&acc)[4][8],
    const float* __restrict__ Ap,      // activations [256][LDA]
    const float* __restrict__ Wrow,    // this thread's weight-row base (length LDA)
    int Klen, int kk0,
    float (&sA)[16][256], float (&sB)[16][32],
    int tid, int mt4, int nt8, int colB)
{
    // register prefetch of chunk kb=0
    const float* ar = Ap + tid * LDA;
    float4 pa0 = *(const float4*)(ar);
    float4 pa1 = *(const float4*)(ar + 4);
    float4 pa2 = *(const float4*)(ar + 8);
    float4 pa3 = *(const float4*)(ar + 12);
    float  pb0 = Wrow[kk0];
    float  pb1 = Wrow[kk0 + 1];

    for (int kb = 0; kb < Klen; kb += 16) {
        // stage into smem (transposed A)
        sA[0][tid]  = pa0.x; sA[1][tid]  = pa0.y; sA[2][tid]  = pa0.z; sA[3][tid]  = pa0.w;
        sA[4][tid]  = pa1.x; sA[5][tid]  = pa1.y; sA[6][tid]  = pa1.z; sA[7][tid]  = pa1.w;
        sA[8][tid]  = pa2.x; sA[9][tid]  = pa2.y; sA[10][tid] = pa2.z; sA[11][tid] = pa2.w;
        sA[12][tid] = pa3.x; sA[13][tid] = pa3.y; sA[14][tid] = pa3.z; sA[15][tid] = pa3.w;
        sB[kk0][colB]     = pb0;
        sB[kk0 + 1][colB] = pb1;
        __syncthreads();

        int kn = kb + 16;
        if (kn < Klen) {                       // prefetch next chunk (overlaps compute)
            const float* ar2 = Ap + tid * LDA + kn;
            pa0 = *(const float4*)(ar2);
            pa1 = *(const float4*)(ar2 + 4);
            pa2 = *(const float4*)(ar2 + 8);
            pa3 = *(const float4*)(ar2 + 12);
            pb0 = Wrow[kn + kk0];
            pb1 = Wrow[kn + kk0 + 1];
        }

        #pragma unroll
        for (int kk = 0; kk < 16; kk++) {
            float4 av = *(const float4*)&sA[kk][mt4];
            float4 b0 = *(const float4*)&sB[kk][nt8];
            float4 b1 = *(const float4*)&sB[kk][nt8 + 4];
            float aa[4] = {av.x, av.y, av.z, av.w};
            float bb[8] = {b0.x, b0.y, b0.z, b0.w, b1.x, b1.y, b1.z, b1.w};
            #pragma unroll
            for (int r = 0; r < 4; r++)
                #pragma unroll
                for (int c = 0; c < 8; c++)
                    acc[r][c] = fmaf(aa[r], bb[c], acc[r][c]);
        }
        __syncthreads();
    }
}

__global__ void __launch_bounds__(256)
lstm_kernel(const float* __restrict__ Wih, const float* __restrict__ Whh,
            const float* __restrict__ Wout, const float* __restrict__ bout,
            float* __restrict__ dout)
{
    __shared__ LstmSmem sm;
    const int tid = threadIdx.x;
    const int cta = blockIdx.x;          // 0..127
    unsigned gen = *((volatile unsigned*)&g_gen);   // replay-safe base generation

    // ---- init state (h0=c0=0, o_prev=0, inp mlp part = mlp[t=0]) ----
    const int gt = cta * 256 + tid;
    for (int i = gt; i < BB * HH; i += NCTA * 256) { g_h[0][i] = 0.f; g_c[i] = 0.f; }
    for (int i = gt; i < BB * AA; i += NCTA * 256)
        g_inp[(i >> 6) * LSTM_IN + 256 + (i & 63)] = 0.f;
    for (int i = gt; i < BB * MLP_O; i += NCTA * 256)
        g_inp[(i >> 8) * LSTM_IN + (i & 255)] = g_mlp[i];
    grid_barrier(gen);

    // thread/tile geometry: CTA owns j in [cta*8, cta*8+8), all 4 gates, all 256 batch rows
    const int j0  = cta * 8;
    const int nt  = tid & 3;             // gate index for GEMM fragment
    const int mt4 = (tid >> 2) * 4;      // batch-row base (4 rows)
    const int nt8 = nt * 8;
    const int colB = tid >> 3;           // 0..31 : B-tile column this thread loads
    const int kk0  = (tid & 7) * 2;
    const int nB   = (colB >> 3) * HH + j0 + (colB & 7);   // weight row for B loads
    const float* WrowIH = Wih + nB * LSTM_IN;
    const float* WrowHH = Whh + nB * HH;

    float biasv[8];
    #pragma unroll
    for (int c = 0; c < 8; c++) biasv[c] = g_bias[nt * HH + j0 + c];

    int cur = 0;
    for (int t = 0; t < SS; ++t) {
        // ---- phase 1: gates GEMM (M=256, N=32 cols = 4 gates x 8 j, K=320+1024) ----
        float acc[4][8];
        #pragma unroll
        for (int r = 0; r < 4; r++)
            #pragma unroll
            for (int c = 0; c < 8; c++) acc[r][c] = 0.f;

        gemm_seg<LSTM_IN>(acc, g_inp,   WrowIH, LSTM_IN, kk0, sm.u.ld.A, sm.u.ld.B, tid, mt4, nt8, colB);
        gemm_seg<HH>     (acc, g_h[cur], WrowHH, HH,     kk0, sm.u.ld.A, sm.u.ld.B, tid, mt4, nt8, colB);

        // gates -> smem [col = gate*8+jl][row = b]
        #pragma unroll
        for (int r = 0; r < 4; r++)
            #pragma unroll
            for (int c = 0; c < 8; c++)
                sm.u.sg[nt8 + c][mt4 + r] = acc[r][c] + biasv[c];
        __syncthreads();

        // ---- phase 2: fused cell update (thread = batch row b, 8 owned j) ----
        const int nxt = cur ^ 1;
        {
            const int b = tid;
            #pragma unroll
            for (int jl = 0; jl < 8; jl++) {
                float iv = sm.u.sg[jl][b];
                float fv = sm.u.sg[8 + jl][b];
                float gv = sm.u.sg[16 + jl][b];
                float ov = sm.u.sg[24 + jl][b];
                iv = 1.f / (1.f + expf(-iv));
                fv = 1.f / (1.f + expf(-fv));
                ov = 1.f / (1.f + expf(-ov));
                gv = tanhf(gv);
                int idx = b * HH + j0 + jl;
                float cnew = fmaf(fv, g_c[idx], iv * gv);
                g_c[idx] = cnew;
                g_h[nxt][idx] = ov * tanhf(cnew);
            }
        }
        grid_barrier(gen);   // h complete chip-wide

        // ---- phase 3: out = h @ Wout^T + bout ; CTA owns b = 2*cta, 2*cta+1 ----
        {
            const float* hb = g_h[nxt];
            int a = tid & 63, q = tid >> 6;                 // q = K quarter
            const float* wr = Wout + a * HH + q * 256;
            const float* h0 = hb + (cta * 2) * HH + q * 256;
            const float* h1 = h0 + HH;
            float s0 = 0.f, s1 = 0.f;
            #pragma unroll 4
            for (int k = 0; k < 256; k += 4) {
                float4 w  = *(const float4*)(wr + k);
                float4 x0 = *(const float4*)(h0 + k);
                float4 x1 = *(const float4*)(h1 + k);
                s0 = fmaf(w.x, x0.x, s0); s0 = fmaf(w.y, x0.y, s0);
                s0 = fmaf(w.z, x0.z, s0); s0 = fmaf(w.w, x0.w, s0);
                s1 = fmaf(w.x, x1.x, s1); s1 = fmaf(w.y, x1.y, s1);
                s1 = fmaf(w.z, x1.z, s1); s1 = fmaf(w.w, x1.w, s1);
            }
            sm.u.red[0][q][a] = s0;
            sm.u.red[1][q][a] = s1;
            __syncthreads();
            if (tid < 128) {
                int bs = tid >> 6, aa2 = tid & 63;
                float v = sm.u.red[bs][0][aa2] + sm.u.red[bs][1][aa2]
                        + sm.u.red[bs][2][aa2] + sm.u.red[bs][3][aa2] + bout[aa2];
                int b = cta * 2 + bs;
                dout[(b * SS + t) * AA + aa2] = v;          // output [B,S,A]
                g_inp[b * LSTM_IN + 256 + aa2] = v;          // o_prev for next step
            }
        }

        // stage mlp[t+1] into g_inp (all CTAs help)
        if (t + 1 < SS) {
            const float* src = g_mlp + (t + 1) * (BB * MLP_O);
            int i = cta * 512 + tid;
            g_inp[(i >> 8) * LSTM_IN + (i & 255)] = src[i];
            i += 256;
            g_inp[(i >> 8) * LSTM_IN + (i & 255)] = src[i];
        }
        grid_barrier(gen);   // o_prev + next-step inputs visible
        cur = nxt;
    }
}

// ---------------- launch ----------------
extern "C" void kernel_launch(void* const* d_in, const int* in_sizes, int n_in,
                              void* d_out, int out_size)
{
    const float* observe  = (const float*)d_in[0];
    const float* obstacle = (const float*)d_in[1];
    const float* mask     = (const float*)d_in[2];
    const float* W1       = (const float*)d_in[3];
    const float* b1       = (const float*)d_in[4];
    const float* W2       = (const float*)d_in[5];
    const float* b2       = (const float*)d_in[6];
    const float* W_ih     = (const float*)d_in[7];
    const float* b_ih     = (const float*)d_in[8];
    const float* W_hh     = (const float*)d_in[9];
    const float* b_hh     = (const float*)d_in[10];
    const float* W_out    = (const float*)d_in[11];
    const float* b_out    = (const float*)d_in[12];
    float* out = (float*)d_out;

    bias_kernel<<<1, 256>>>(W2, b1, b2, b_ih, b_hh);
    collapse_kernel<<<IN_D, 256>>>(W1, W2);
    mlp_kernel<<<(BB * SS) / MLP_TILE, 256>>>(observe, obstacle, mask);
    lstm_kernel<<<NCTA, 256>>>(W_ih, W_hh, W_out, b_out, out);
}

// round 3
// speedup vs baseline: 1.4503x; 1.4503x over previous
#include <cuda_runtime.h>
#include <math.h>
#include <stdint.h>

// Problem constants
#define BB    256     // batch
#define SS    128     // seq len
#define IN_D  192
#define MLP_O 256
#define HH    1024
#define AA    64
#define LSTM_IN 320   // MLP_O + A
#define KTOT  1344    // LSTM_IN + HH (fused K)
#define G4    4096    // 4*H
#define NCTA  128     // persistent LSTM grid

// smem geometry (floats)
#define WSTRIDE 1348              // 1344 + 4 pad  (conflict-free B frags)
#define ASTRIDE 36                // 32 + 4 pad    (conflict-free A frags)
#define SW_FLOATS (32 * WSTRIDE)  // 43136
#define SA_FLOATS (BB * ASTRIDE)  // 9216
#define SMEM_BYTES ((SW_FLOATS + SA_FLOATS) * 4)   // 209408

// ---------------- device scratch ----------------
__device__ __align__(16) float g_WcT[IN_D * MLP_O];
__device__ float g_bc[MLP_O];
__device__ float g_bias[G4];
__device__ __align__(16) float g_mlp[SS * BB * MLP_O];   // tf32-rounded
__device__ __align__(16) float g_act[2][BB * KTOT];      // [mlp | o_prev | h], tf32-rounded
__device__ __align__(16) float g_c[BB * HH];
__device__ unsigned g_cnt = 0;
__device__ unsigned g_gen = 0;

__device__ __forceinline__ float tf32r(float x)
{
    uint32_t y;
    asm("cvt.rna.tf32.f32 %0, %1;" : "=r"(y) : "f"(x));
    return __uint_as_float(y);
}

__device__ __forceinline__ void mma_tf32(float c[4],
                                         uint32_t a0, uint32_t a1, uint32_t a2, uint32_t a3,
                                         uint32_t b0, uint32_t b1)
{
    asm("mma.sync.aligned.m16n8k8.row.col.f32.tf32.tf32.f32 "
        "{%0,%1,%2,%3}, {%4,%5,%6,%7}, {%8,%9}, {%0,%1,%2,%3};"
        : "+f"(c[0]), "+f"(c[1]), "+f"(c[2]), "+f"(c[3])
        : "r"(a0), "r"(a1), "r"(a2), "r"(a3), "r"(b0), "r"(b1));
}

// ---------------- grid barrier (replay-safe) ----------------
__device__ __forceinline__ void grid_barrier(unsigned &gen)
{
    __syncthreads();
    if (threadIdx.x == 0) {
        __threadfence();
        unsigned ticket = atomicAdd(&g_cnt, 1u);
        if (ticket == NCTA - 1u) {
            g_cnt = 0u;
            __threadfence();
            atomicAdd(&g_gen, 1u);
        } else {
            while (*((volatile unsigned *)&g_gen) == gen) { }
            __threadfence();
        }
    }
    gen += 1u;
    __syncthreads();
}

// ---------------- kernel 0: biases ----------------
__global__ void bias_kernel(const float* __restrict__ W2, const float* __restrict__ b1,
                            const float* __restrict__ b2, const float* __restrict__ bih,
                            const float* __restrict__ bhh)
{
    int tid = threadIdx.x;
    for (int n = tid; n < G4; n += 256) g_bias[n] = bih[n] + bhh[n];
    const float* w2r = W2 + tid * 1024;
    float acc = b2[tid];
    #pragma unroll 4
    for (int h = 0; h < 1024; h += 4) {
        float4 w = *(const float4*)(w2r + h);
        acc = fmaf(w.x, b1[h], acc);
        acc = fmaf(w.y, b1[h+1], acc);
        acc = fmaf(w.z, b1[h+2], acc);
        acc = fmaf(w.w, b1[h+3], acc);
    }
    g_bc[tid] = acc;
}

// ---------------- kernel 1: collapse W2@W1 -> WcT[k][o] ----------------
__global__ void collapse_kernel(const float* __restrict__ W1, const float* __restrict__ W2)
{
    __shared__ float w1k[1024];
    int k = blockIdx.x;
    for (int h = threadIdx.x; h < 1024; h += 256) w1k[h] = W1[h * IN_D + k];
    __syncthreads();
    int o = threadIdx.x;
    const float* w2r = W2 + o * 1024;
    float acc = 0.f;
    #pragma unroll 4
    for (int h = 0; h < 1024; h += 4) {
        float4 w = *(const float4*)(w2r + h);
        acc = fmaf(w.x, w1k[h],   acc);
        acc = fmaf(w.y, w1k[h+1], acc);
        acc = fmaf(w.z, w1k[h+2], acc);
        acc = fmaf(w.w, w1k[h+3], acc);
    }
    g_WcT[k * MLP_O + o] = acc;
}

// ---------------- kernel 2: mlp = relu(x @ Wc^T + bc), tf32-rounded ----------------
#define MLP_TILE 16
__global__ void mlp_kernel(const float* __restrict__ observe,
                           const float* __restrict__ obstacle,
                           const float* __restrict__ mask)
{
    __shared__ float xs[MLP_TILE * IN_D];
    int tid = threadIdx.x;
    int p0 = blockIdx.x * MLP_TILE;
    for (int idx = tid; idx < MLP_TILE * IN_D; idx += 256) {
        int i = idx / IN_D, k = idx - i * IN_D;
        int p = p0 + i;
        float v;
        if (k < 64) {
            v = observe[p * 64 + k];
        } else {
            int kk = k - 64;
            int n = kk >> 4;
            v = obstacle[p * 128 + kk] * mask[p * 8 + n];
        }
        xs[i * IN_D + k] = v;
    }
    __syncthreads();

    float acc[MLP_TILE];
    #pragma unroll
    for (int i = 0; i < MLP_TILE; i++) acc[i] = 0.f;
    #pragma unroll 4
    for (int k = 0; k < IN_D; k++) {
        float w = g_WcT[k * MLP_O + tid];
        #pragma unroll
        for (int i = 0; i < MLP_TILE; i++)
            acc[i] = fmaf(xs[i * IN_D + k], w, acc[i]);
    }
    float bcv = g_bc[tid];
    #pragma unroll
    for (int i = 0; i < MLP_TILE; i++) {
        int p = p0 + i;
        int b = p >> 7, s = p & 127;
        g_mlp[(s * BB + b) * MLP_O + tid] = tf32r(fmaxf(acc[i] + bcv, 0.f));
    }
}

// ---------------- persistent LSTM kernel (tf32 mma) ----------------
__global__ void __launch_bounds__(256, 1)
lstm_kernel(const float* __restrict__ Wih, const float* __restrict__ Whh,
            const float* __restrict__ Wout, const float* __restrict__ bout,
            float* __restrict__ dout)
{
    extern __shared__ float smem[];
    float* sW = smem;                 // [32][WSTRIDE] persistent weights (tf32)
    float* sA = smem + SW_FLOATS;     // [256][ASTRIDE] activation chunk; aliased below
    float* sg = sA;                   // [32][257] gate staging (8224 <= 9216 floats)
    float* red = sA;                  // [2][4][64] output reduction

    const int tid  = threadIdx.x;
    const int cta  = blockIdx.x;
    const int lane = tid & 31;
    const int w    = tid >> 5;        // warp 0..7 -> rows [w*32, w*32+32)
    const int gid  = lane >> 2;
    const int tig  = lane & 3;
    const int j0   = cta * 8;
    unsigned gen = *((volatile unsigned*)&g_gen);

    // ---- load this CTA's 32 weight rows into smem (tf32-rounded), once ----
    for (int idx = tid; idx < 32 * KTOT; idx += 256) {
        int col = idx / KTOT, k = idx - col * KTOT;
        int row = (col >> 3) * HH + j0 + (col & 7);   // gate*1024 + j
        float v = (k < LSTM_IN) ? Wih[row * LSTM_IN + k]
                                : Whh[row * HH + (k - LSTM_IN)];
        sW[col * WSTRIDE + k] = tf32r(v);
    }

    // ---- init global state: g_act[0] = [mlp_0 | 0 | 0], c = 0 ----
    const int gt = cta * 256 + tid;
    for (int i = gt; i < BB * HH; i += NCTA * 256) g_c[i] = 0.f;
    for (int i = gt; i < BB * (64 + HH); i += NCTA * 256) {
        int b = i / 1088, c = i - b * 1088;
        g_act[0][b * KTOT + 256 + c] = 0.f;
    }
    for (int i = gt; i < BB * MLP_O; i += NCTA * 256)
        g_act[0][(i >> 8) * KTOT + (i & 255)] = g_mlp[i];
    grid_barrier(gen);

    // bias regs for this thread's C-fragment columns: cols nt*8 + 2*tig + {0,1}
    float biasv[4][2];
    #pragma unroll
    for (int nt = 0; nt < 4; nt++) {
        biasv[nt][0] = g_bias[nt * HH + j0 + 2 * tig];
        biasv[nt][1] = g_bias[nt * HH + j0 + 2 * tig + 1];
    }

    int cur = 0;
    for (int t = 0; t < SS; ++t) {
        const float* act = g_act[cur];
        // ---- phase 1: gates GEMM  (M=256, N=32, K=1344) via tf32 mma ----
        float acc[2][4][4];
        #pragma unroll
        for (int mt = 0; mt < 2; mt++)
            #pragma unroll
            for (int nt = 0; nt < 4; nt++)
                #pragma unroll
                for (int r = 0; r < 4; r++) acc[mt][nt][r] = 0.f;

        // register prefetch of chunk 0 (each thread owns batch row = tid)
        const float4* arow = (const float4*)(act + tid * KTOT);
        float4 pf[8];
        #pragma unroll
        for (int q = 0; q < 8; q++) pf[q] = arow[q];

        for (int cc = 0; cc < KTOT / 32; ++cc) {
            // stage chunk into smem
            float* dst = sA + tid * ASTRIDE;
            #pragma unroll
            for (int q = 0; q < 8; q++) *(float4*)(dst + q * 4) = pf[q];
            __syncthreads();

            if (cc + 1 < KTOT / 32) {
                #pragma unroll
                for (int q = 0; q < 8; q++) pf[q] = arow[(cc + 1) * 8 + q];
            }

            const int kbase = cc * 32;
            #pragma unroll
            for (int ks = 0; ks < 4; ks++) {
                const int kk = ks * 8;
                // B frags (shared across m-tiles): col = nt*8+gid, k = tig / tig+4
                uint32_t b0[4], b1[4];
                #pragma unroll
                for (int nt = 0; nt < 4; nt++) {
                    const float* wp = sW + (nt * 8 + gid) * WSTRIDE + kbase + kk + tig;
                    b0[nt] = __float_as_uint(wp[0]);
                    b1[nt] = __float_as_uint(wp[4]);
                }
                #pragma unroll
                for (int mt = 0; mt < 2; mt++) {
                    const float* ap = sA + (w * 32 + mt * 16 + gid) * ASTRIDE + kk + tig;
                    uint32_t a0 = __float_as_uint(ap[0]);
                    uint32_t a1 = __float_as_uint(ap[8 * ASTRIDE]);
                    uint32_t a2 = __float_as_uint(ap[4]);
                    uint32_t a3 = __float_as_uint(ap[8 * ASTRIDE + 4]);
                    #pragma unroll
                    for (int nt = 0; nt < 4; nt++)
                        mma_tf32(acc[mt][nt], a0, a1, a2, a3, b0[nt], b1[nt]);
                }
            }
            __syncthreads();
        }

        // ---- gates + bias -> smem sg[col][b] ----
        #pragma unroll
        for (int mt = 0; mt < 2; mt++) {
            int r0 = w * 32 + mt * 16 + gid;
            #pragma unroll
            for (int nt = 0; nt < 4; nt++) {
                int c0 = nt * 8 + 2 * tig;
                sg[c0 * 257 + r0]           = acc[mt][nt][0] + biasv[nt][0];
                sg[(c0 + 1) * 257 + r0]     = acc[mt][nt][1] + biasv[nt][1];
                sg[c0 * 257 + r0 + 8]       = acc[mt][nt][2] + biasv[nt][0];
                sg[(c0 + 1) * 257 + r0 + 8] = acc[mt][nt][3] + biasv[nt][1];
            }
        }
        __syncthreads();

        // ---- phase 2: fused cell update (thread = batch row, 8 owned j) ----
        const int nxt = cur ^ 1;
        {
            const int b = tid;
            #pragma unroll
            for (int jl = 0; jl < 8; jl++) {
                float iv = sg[jl * 257 + b];
                float fv = sg[(8 + jl) * 257 + b];
                float gv = sg[(16 + jl) * 257 + b];
                float ov = sg[(24 + jl) * 257 + b];
                iv = 1.f / (1.f + expf(-iv));
                fv = 1.f / (1.f + expf(-fv));
                ov = 1.f / (1.f + expf(-ov));
                gv = tanhf(gv);
                int idx = b * HH + j0 + jl;
                float cnew = fmaf(fv, g_c[idx], iv * gv);
                g_c[idx] = cnew;
                g_act[nxt][b * KTOT + LSTM_IN + j0 + jl] = tf32r(ov * tanhf(cnew));
            }
        }
        grid_barrier(gen);   // h complete chip-wide

        // ---- phase 3: out = h @ Wout^T + bout ; CTA owns b = 2*cta, 2*cta+1 ----
        {
            const float* hb = g_act[nxt];
            int a = tid & 63, q = tid >> 6;
            const float* wr = Wout + a * HH + q * 256;
            const float* h0 = hb + (cta * 2) * KTOT + LSTM_IN + q * 256;
            const float* h1 = h0 + KTOT;
            float s0 = 0.f, s1 = 0.f;
            #pragma unroll 4
            for (int k = 0; k < 256; k += 4) {
                float4 ww = *(const float4*)(wr + k);
                float4 x0 = *(const float4*)(h0 + k);
                float4 x1 = *(const float4*)(h1 + k);
                s0 = fmaf(ww.x, x0.x, s0); s0 = fmaf(ww.y, x0.y, s0);
                s0 = fmaf(ww.z, x0.z, s0); s0 = fmaf(ww.w, x0.w, s0);
                s1 = fmaf(ww.x, x1.x, s1); s1 = fmaf(ww.y, x1.y, s1);
                s1 = fmaf(ww.z, x1.z, s1); s1 = fmaf(ww.w, x1.w, s1);
            }
            red[(0 * 4 + q) * 64 + a] = s0;
            red[(1 * 4 + q) * 64 + a] = s1;
            __syncthreads();
            if (tid < 128) {
                int bs = tid >> 6, aa2 = tid & 63;
                float v = red[(bs * 4 + 0) * 64 + aa2] + red[(bs * 4 + 1) * 64 + aa2]
                        + red[(bs * 4 + 2) * 64 + aa2] + red[(bs * 4 + 3) * 64 + aa2]
                        + bout[aa2];
                int b = cta * 2 + bs;
                dout[(b * SS + t) * AA + aa2] = v;
                g_act[nxt][b * KTOT + 256 + aa2] = tf32r(v);   // o_prev
            }
        }

        // stage mlp[t+1] into g_act[nxt]
        if (t + 1 < SS) {
            const float* src = g_mlp + (t + 1) * (BB * MLP_O);
            int i = cta * 512 + tid;
            g_act[nxt][(i >> 8) * KTOT + (i & 255)] = src[i];
            i += 256;
            g_act[nxt][(i >> 8) * KTOT + (i & 255)] = src[i];
        }
        grid_barrier(gen);
        cur = nxt;
    }
}

// ---------------- launch ----------------
extern "C" void kernel_launch(void* const* d_in, const int* in_sizes, int n_in,
                              void* d_out, int out_size)
{
    const float* observe  = (const float*)d_in[0];
    const float* obstacle = (const float*)d_in[1];
    const float* mask     = (const float*)d_in[2];
    const float* W1       = (const float*)d_in[3];
    const float* b1       = (const float*)d_in[4];
    const float* W2       = (const float*)d_in[5];
    const float* b2       = (const float*)d_in[6];
    const float* W_ih     = (const float*)d_in[7];
    const float* b_ih     = (const float*)d_in[8];
    const float* W_hh     = (const float*)d_in[9];
    const float* b_hh     = (const float*)d_in[10];
    const float* W_out    = (const float*)d_in[11];
    const float* b_out    = (const float*)d_in[12];
    float* out = (float*)d_out;

    cudaFuncSetAttribute(lstm_kernel, cudaFuncAttributeMaxDynamicSharedMemorySize, SMEM_BYTES);

    bias_kernel<<<1, 256>>>(W2, b1, b2, b_ih, b_hh);
    collapse_kernel<<<IN_D, 256>>>(W1, W2);
    mlp_kernel<<<(BB * SS) / MLP_TILE, 256>>>(observe, obstacle, mask);
    lstm_kernel<<<NCTA, 256, SMEM_BYTES>>>(W_ih, W_hh, W_out, b_out, out);
}

// round 4
// speedup vs baseline: 3.7431x; 2.5810x over previous
#include <cuda_runtime.h>
#include <math.h>
#include <stdint.h>

// Problem constants
#define BB    256
#define SS    128
#define IN_D  192
#define MLP_O 256
#define HH    1024
#define AA    64
#define K2    1280          // MLP_O + HH (o_prev folded away)
#define NCH   40            // K2/32 chunks
#define G4    4096
#define NCTA  128

// lstm smem stage geometry (floats)
#define AS    264           // A stage stride [32 k][264]
#define BS_   36            // B stage stride [32 col][36]
#define STG_A (32*AS)       // 8448
#define STG_B (32*BS_)      // 1152
#define STG   (STG_A+STG_B) // 9600
#define NSTG  4
#define SMEM_BYTES (NSTG*STG*4)   // 153600

// ---------------- device scratch ----------------
__device__ __align__(16) float g_WcT[IN_D * MLP_O];
__device__ float g_bc[MLP_O];
__device__ float g_bias0[G4];        // b_ih + b_hh              (t == 0)
__device__ float g_bias1[G4];        // + W_ihA @ bout           (t >= 1)
__device__ __align__(16) float g_Wp[NCTA * NCH * 32 * 32];       // packed tf32 weights, 21MB
__device__ __align__(16) float g_AT[(SS + 1) * K2 * BB];         // [t][k][b] slabs, 169MB
__device__ __align__(16) float g_c[HH * BB];                     // [j][b]
__device__ unsigned g_cnt = 0;
__device__ unsigned g_gen = 0;

__device__ __forceinline__ float tf32r(float x)
{
    uint32_t y;
    asm("cvt.rna.tf32.f32 %0, %1;" : "=r"(y) : "f"(x));
    return __uint_as_float(y);
}

__device__ __forceinline__ void mma_tf32(float c[4],
                                         uint32_t a0, uint32_t a1, uint32_t a2, uint32_t a3,
                                         uint32_t b0, uint32_t b1)
{
    asm("mma.sync.aligned.m16n8k8.row.col.f32.tf32.tf32.f32 "
        "{%0,%1,%2,%3}, {%4,%5,%6,%7}, {%8,%9}, {%0,%1,%2,%3};"
        : "+f"(c[0]), "+f"(c[1]), "+f"(c[2]), "+f"(c[3])
        : "r"(a0), "r"(a1), "r"(a2), "r"(a3), "r"(b0), "r"(b1));
}

__device__ __forceinline__ uint32_t smem_u32(const void* p)
{
    uint32_t a;
    asm("{ .reg .u64 t; cvta.to.shared.u64 t, %1; cvt.u32.u64 %0, t; }" : "=r"(a) : "l"(p));
    return a;
}

__device__ __forceinline__ void cpasync16(uint32_t dst, const void* src)
{
    asm volatile("cp.async.cg.shared.global [%0], [%1], 16;" :: "r"(dst), "l"(src));
}
#define CP_COMMIT() asm volatile("cp.async.commit_group;")
#define CP_WAIT(N)  asm volatile("cp.async.wait_group %0;" :: "n"(N))

// ---------------- grid barrier ----------------
__device__ __forceinline__ void grid_barrier(unsigned &gen)
{
    __syncthreads();
    if (threadIdx.x == 0) {
        __threadfence();
        unsigned ticket = atomicAdd(&g_cnt, 1u);
        if (ticket == NCTA - 1u) {
            g_cnt = 0u;
            __threadfence();
            atomicAdd(&g_gen, 1u);
        } else {
            while (*((volatile unsigned *)&g_gen) == gen) { }
            __threadfence();
        }
    }
    gen += 1u;
    __syncthreads();
}

// ---------------- kernel 0: biases (+ collapsed MLP bias in block 0) ----------------
__global__ void bias_kernel(const float* __restrict__ W2, const float* __restrict__ b1,
                            const float* __restrict__ b2, const float* __restrict__ bih,
                            const float* __restrict__ bhh, const float* __restrict__ Wih,
                            const float* __restrict__ bout)
{
    int n = blockIdx.x * 256 + threadIdx.x;   // 0..4095
    float base = bih[n] + bhh[n];
    float fold = 0.f;
    const float* wa = Wih + n * 320 + 256;
    #pragma unroll
    for (int a = 0; a < 64; a++) fold = fmaf(wa[a], bout[a], fold);
    g_bias0[n] = base;
    g_bias1[n] = base + fold;

    if (blockIdx.x == 0) {
        int tid = threadIdx.x;
        const float* w2r = W2 + tid * 1024;
        float acc = b2[tid];
        #pragma unroll 4
        for (int h = 0; h < 1024; h += 4) {
            float4 w = *(const float4*)(w2r + h);
            acc = fmaf(w.x, b1[h], acc);
            acc = fmaf(w.y, b1[h+1], acc);
            acc = fmaf(w.z, b1[h+2], acc);
            acc = fmaf(w.w, b1[h+3], acc);
        }
        g_bc[tid] = acc;
    }
}

// ---------------- kernel 1: collapse W2@W1 -> WcT[k][o] ----------------
__global__ void collapse_kernel(const float* __restrict__ W1, const float* __restrict__ W2)
{
    __shared__ float w1k[1024];
    int k = blockIdx.x;
    for (int h = threadIdx.x; h < 1024; h += 256) w1k[h] = W1[h * IN_D + k];
    __syncthreads();
    int o = threadIdx.x;
    const float* w2r = W2 + o * 1024;
    float acc = 0.f;
    #pragma unroll 4
    for (int h = 0; h < 1024; h += 4) {
        float4 w = *(const float4*)(w2r + h);
        acc = fmaf(w.x, w1k[h],   acc);
        acc = fmaf(w.y, w1k[h+1], acc);
        acc = fmaf(w.z, w1k[h+2], acc);
        acc = fmaf(w.w, w1k[h+3], acc);
    }
    g_WcT[k * MLP_O + o] = acc;
}

// ---------------- kernel 2: pack fused+folded weights (tf32) ----------------
// g_Wp[cta][ch][col][kk]; col = gate*8 + jl; row = gate*1024 + cta*8 + jl
// k < 256 : W_ih[row][k]
// k >= 256: W_hh[row][k-256] + (W_ih[row][256:320] @ Wout)[k-256]
__global__ void wprep_kernel(const float* __restrict__ Wih, const float* __restrict__ Whh,
                             const float* __restrict__ Wout)
{
    __shared__ float As[32 * 64];       // W_ihA rows for our 32 cols
    __shared__ float Wc[64 * 132];      // Wout chunk [a][128h]
    const int cta = blockIdx.x;
    const int tid = threadIdx.x;
    float* wp = g_Wp + (size_t)cta * NCH * 1024;

    // A_s
    #pragma unroll
    for (int q = 0; q < 8; q++) {
        int idx = q * 256 + tid;
        int col = idx >> 6, a = idx & 63;
        int row = (col >> 3) * 1024 + cta * 8 + (col & 7);
        As[col * 64 + a] = Wih[row * 320 + 256 + a];
    }
    // part 1: k < 256
    #pragma unroll 4
    for (int q = 0; q < 32; q++) {
        int idx = q * 256 + tid;
        int col = idx >> 8, k = idx & 255;
        int row = (col >> 3) * 1024 + cta * 8 + (col & 7);
        wp[((k >> 5) * 32 + col) * 32 + (k & 31)] = tf32r(Wih[row * 320 + k]);
    }
    __syncthreads();

    const int col = tid >> 3;
    const int hb  = tid & 7;
    const int row = (col >> 3) * 1024 + cta * 8 + (col & 7);
    for (int hc = 0; hc < 8; hc++) {
        #pragma unroll 4
        for (int q = 0; q < 32; q++) {
            int idx = q * 256 + tid;
            int a = idx >> 7, h = idx & 127;
            Wc[a * 132 + h] = Wout[a * 1024 + hc * 128 + h];
        }
        __syncthreads();
        #pragma unroll
        for (int i = 0; i < 16; i++) {
            int h = hb * 16 + i;
            int hh = hc * 128 + h;
            float fold = 0.f;
            #pragma unroll 8
            for (int a = 0; a < 64; a++)
                fold = fmaf(As[col * 64 + a], Wc[a * 132 + h], fold);
            float val = Whh[row * 1024 + hh] + fold;
            int k = 256 + hh;
            wp[((k >> 5) * 32 + col) * 32 + (k & 31)] = tf32r(val);
        }
        __syncthreads();
    }
}

// ---------------- kernel 3: mlp -> g_AT[s][o][b] (transposed, tf32) ----------------
__global__ void mlp_kernel(const float* __restrict__ observe,
                           const float* __restrict__ obstacle,
                           const float* __restrict__ mask)
{
    __shared__ float xs[16 * IN_D];
    const int tid = threadIdx.x;
    const int s   = blockIdx.x >> 4;
    const int b0  = (blockIdx.x & 15) * 16;
    for (int idx = tid; idx < 16 * IN_D; idx += 256) {
        int i = idx / IN_D, k = idx - i * IN_D;
        int p = (b0 + i) * 128 + s;
        float v;
        if (k < 64) v = observe[p * 64 + k];
        else {
            int kk = k - 64;
            v = obstacle[p * 128 + kk] * mask[p * 8 + (kk >> 4)];
        }
        xs[i * IN_D + k] = v;
    }
    __syncthreads();

    float acc[16];
    #pragma unroll
    for (int i = 0; i < 16; i++) acc[i] = 0.f;
    #pragma unroll 4
    for (int k = 0; k < IN_D; k++) {
        float w = g_WcT[k * MLP_O + tid];
        #pragma unroll
        for (int i = 0; i < 16; i++)
            acc[i] = fmaf(xs[i * IN_D + k], w, acc[i]);
    }
    float bcv = g_bc[tid];
    float* dst = g_AT + (size_t)s * K2 * BB + tid * BB + b0;
    #pragma unroll
    for (int i = 0; i < 16; i++)
        dst[i] = tf32r(fmaxf(acc[i] + bcv, 0.f));
}

// ---------------- kernel 4: persistent LSTM ----------------
__global__ void __launch_bounds__(256, 1)
lstm_kernel(int dummy)
{
    extern __shared__ float smem[];
    float* sg = smem;                 // gate staging aliases stage 0

    const int tid  = threadIdx.x;
    const int cta  = blockIdx.x;
    const int lane = tid & 31;
    const int w    = tid >> 5;
    const int gid  = lane >> 2;
    const int tig  = lane & 3;
    const int j0   = cta * 8;
    unsigned gen = *((volatile unsigned*)&g_gen);

    // cp.async source/dst geometry
    const int arow = tid >> 3;              // A stage row 0..31
    const int au   = tid & 7;               // 16B unit group
    const uint32_t sbase = smem_u32(smem);
    const int bcol = tid >> 3, bkk = (tid & 7) * 4;
    const float* wpk = g_Wp + (size_t)cta * NCH * 1024;

    // init: zero h-part of slab 0 and c
    const int gt = cta * 256 + tid;
    for (int i = gt; i < HH * BB; i += NCTA * 256) {
        g_c[i] = 0.f;
        g_AT[(size_t)MLP_O * BB + i] = 0.f;   // slab 0, rows 256..1280
    }
    grid_barrier(gen);

    float bias0[4][2], bias1[4][2];
    #pragma unroll
    for (int nt = 0; nt < 4; nt++) {
        int c0 = nt * HH + j0 + 2 * tig;
        bias0[nt][0] = g_bias0[c0];     bias0[nt][1] = g_bias0[c0 + 1];
        bias1[nt][0] = g_bias1[c0];     bias1[nt][1] = g_bias1[c0 + 1];
    }

    for (int t = 0; t < SS; ++t) {
        const float* Aslab = g_AT + (size_t)t * K2 * BB;

        // ---- pipelined GEMM: M=256, N=32, K=1280 ----
        float acc[2][4][4];
        #pragma unroll
        for (int mt = 0; mt < 2; mt++)
            #pragma unroll
            for (int nt = 0; nt < 4; nt++)
                #pragma unroll
                for (int r = 0; r < 4; r++) acc[mt][nt][r] = 0.f;

        // prologue: stages 0..2
        #pragma unroll
        for (int s = 0; s < 3; s++) {
            uint32_t sdA = sbase + (s * STG) * 4;
            uint32_t sdB = sbase + (s * STG + STG_A) * 4;
            const float* srcA = Aslab + s * 32 * BB;
            #pragma unroll
            for (int q = 0; q < 8; q++) {
                int u = au + q * 8;         // 16B unit in row
                cpasync16(sdA + (arow * AS + u * 4) * 4, srcA + arow * BB + u * 4);
            }
            cpasync16(sdB + (bcol * BS_ + bkk) * 4, wpk + s * 1024 + tid * 4);
            CP_COMMIT();
        }

        for (int cc = 0; cc < NCH; cc++) {
            if (cc + 3 < NCH) CP_WAIT(2); else CP_WAIT(0);
            __syncthreads();
            if (cc + 3 < NCH) {
                int s = (cc + 3) & 3;
                uint32_t sdA = sbase + (s * STG) * 4;
                uint32_t sdB = sbase + (s * STG + STG_A) * 4;
                const float* srcA = Aslab + (cc + 3) * 32 * BB;
                #pragma unroll
                for (int q = 0; q < 8; q++) {
                    int u = au + q * 8;
                    cpasync16(sdA + (arow * AS + u * 4) * 4, srcA + arow * BB + u * 4);
                }
                cpasync16(sdB + (bcol * BS_ + bkk) * 4, wpk + (cc + 3) * 1024 + tid * 4);
                CP_COMMIT();
            }
            const float* sA = smem + (cc & 3) * STG;
            const float* sB = sA + STG_A;
            #pragma unroll
            for (int ks = 0; ks < 4; ks++) {
                const int kk = ks * 8;
                uint32_t b0[4], b1[4];
                #pragma unroll
                for (int nt = 0; nt < 4; nt++) {
                    const float* wp2 = sB + (nt * 8 + gid) * BS_ + kk + tig;
                    b0[nt] = __float_as_uint(wp2[0]);
                    b1[nt] = __float_as_uint(wp2[4]);
                }
                #pragma unroll
                for (int mt = 0; mt < 2; mt++) {
                    const float* ap = sA + (kk + tig) * AS + w * 32 + mt * 16 + gid;
                    uint32_t a0 = __float_as_uint(ap[0]);
                    uint32_t a1 = __float_as_uint(ap[8]);
                    uint32_t a2 = __float_as_uint(ap[4 * AS]);
                    uint32_t a3 = __float_as_uint(ap[4 * AS + 8]);
                    #pragma unroll
                    for (int nt = 0; nt < 4; nt++)
                        mma_tf32(acc[mt][nt], a0, a1, a2, a3, b0[nt], b1[nt]);
                }
            }
        }
        __syncthreads();   // all warps done with stage buffers -> reuse as sg

        // gates + bias -> sg[col][b]
        #pragma unroll
        for (int mt = 0; mt < 2; mt++) {
            int r0 = w * 32 + mt * 16 + gid;
            #pragma unroll
            for (int nt = 0; nt < 4; nt++) {
                int c0 = nt * 8 + 2 * tig;
                float bv0 = (t == 0) ? bias0[nt][0] : bias1[nt][0];
                float bv1 = (t == 0) ? bias0[nt][1] : bias1[nt][1];
                sg[c0 * 257 + r0]           = acc[mt][nt][0] + bv0;
                sg[(c0 + 1) * 257 + r0]     = acc[mt][nt][1] + bv1;
                sg[c0 * 257 + r0 + 8]       = acc[mt][nt][2] + bv0;
                sg[(c0 + 1) * 257 + r0 + 8] = acc[mt][nt][3] + bv1;
            }
        }
        __syncthreads();

        // cell update: thread = batch row b, 8 owned j
        {
            const int b = tid;
            float* hdst = g_AT + (size_t)(t + 1) * K2 * BB + (MLP_O + j0) * BB + b;
            #pragma unroll
            for (int jl = 0; jl < 8; jl++) {
                float iv = sg[jl * 257 + b];
                float fv = sg[(8 + jl) * 257 + b];
                float gv = sg[(16 + jl) * 257 + b];
                float ov = sg[(24 + jl) * 257 + b];
                iv = 1.f / (1.f + expf(-iv));
                fv = 1.f / (1.f + expf(-fv));
                ov = 1.f / (1.f + expf(-ov));
                gv = tanhf(gv);
                int ci = (j0 + jl) * BB + b;
                float cnew = fmaf(fv, g_c[ci], iv * gv);
                g_c[ci] = cnew;
                hdst[jl * BB] = tf32r(ov * tanhf(cnew));
            }
        }
        grid_barrier(gen);
    }
}

// ---------------- kernel 5: out[b][t][a] = h_t @ Wout^T + bout ----------------
__global__ void finalout_kernel(const float* __restrict__ Wout,
                                const float* __restrict__ bout,
                                float* __restrict__ dout)
{
    __shared__ float sH[32 * 132];      // [k][128 b]
    __shared__ float sWT[32 * 68];      // [k][64 a]
    const int tid = threadIdx.x;
    const int tt  = blockIdx.x >> 1;
    const int b0  = (blockIdx.x & 1) * 128;
    const int b   = tid & 127;
    const int ab  = (tid >> 7) * 32;    // a base (0 or 32)

    const float* hsl = g_AT + (size_t)(tt + 1) * K2 * BB + MLP_O * BB;

    float acc[32];
    #pragma unroll
    for (int r = 0; r < 32; r++) acc[r] = 0.f;

    for (int jc = 0; jc < 32; jc++) {
        #pragma unroll
        for (int q = 0; q < 16; q++) {
            int idx = q * 256 + tid;
            int k = idx >> 7, bb2 = idx & 127;
            sH[k * 132 + bb2] = hsl[(jc * 32 + k) * BB + b0 + bb2];
        }
        #pragma unroll
        for (int q = 0; q < 8; q++) {
            int idx = q * 256 + tid;
            int a = idx >> 5, j = idx & 31;
            sWT[j * 68 + a] = Wout[a * 1024 + jc * 32 + j];
        }
        __syncthreads();
        #pragma unroll 4
        for (int k = 0; k < 32; k++) {
            float av = sH[k * 132 + b];
            const float4* wp = (const float4*)(sWT + k * 68 + ab);
            #pragma unroll
            for (int r = 0; r < 8; r++) {
                float4 wv = wp[r];
                acc[r*4+0] = fmaf(av, wv.x, acc[r*4+0]);
                acc[r*4+1] = fmaf(av, wv.y, acc[r*4+1]);
                acc[r*4+2] = fmaf(av, wv.z, acc[r*4+2]);
                acc[r*4+3] = fmaf(av, wv.w, acc[r*4+3]);
            }
        }
        __syncthreads();
    }
    float* dp = dout + (size_t)(b0 + b) * SS * AA + tt * AA + ab;
    #pragma unroll
    for (int r = 0; r < 32; r++) dp[r] = acc[r] + bout[ab + r];
}

// ---------------- launch ----------------
extern "C" void kernel_launch(void* const* d_in, const int* in_sizes, int n_in,
                              void* d_out, int out_size)
{
    const float* observe  = (const float*)d_in[0];
    const float* obstacle = (const float*)d_in[1];
    const float* mask     = (const float*)d_in[2];
    const float* W1       = (const float*)d_in[3];
    const float* b1       = (const float*)d_in[4];
    const float* W2       = (const float*)d_in[5];
    const float* b2       = (const float*)d_in[6];
    const float* W_ih     = (const float*)d_in[7];
    const float* b_ih     = (const float*)d_in[8];
    const float* W_hh     = (const float*)d_in[9];
    const float* b_hh     = (const float*)d_in[10];
    const float* W_out    = (const float*)d_in[11];
    const float* b_out    = (const float*)d_in[12];
    float* out = (float*)d_out;

    cudaFuncSetAttribute(lstm_kernel, cudaFuncAttributeMaxDynamicSharedMemorySize, SMEM_BYTES);

    bias_kernel<<<16, 256>>>(W2, b1, b2, b_ih, b_hh, W_ih, b_out);
    collapse_kernel<<<IN_D, 256>>>(W1, W2);
    wprep_kernel<<<NCTA, 256>>>(W_ih, W_hh, W_out);
    mlp_kernel<<<SS * 16, 256>>>(observe, obstacle, mask);
    lstm_kernel<<<NCTA, 256, SMEM_BYTES>>>(0);
    finalout_kernel<<<SS * 2, 256>>>(W_out, b_out, out);
}

// round 6
// speedup vs baseline: 5.8785x; 1.5705x over previous
#include <cuda_runtime.h>
#include <cuda_fp16.h>
#include <math.h>
#include <stdint.h>

// Problem constants
#define BB    256
#define SS    128
#define IN_D  192
#define MLP_O 256
#define HH    1024
#define AA    64
#define K2    1280          // MLP_O + HH (o_prev folded away)
#define CK    64            // K per chunk
#define NCH   20            // K2/CK
#define G4    4096
#define NCTA  128

// lstm smem stage geometry (halfs)
#define AS2   72            // padded k-stride (144B rows: conflict-free ldmatrix)
#define STG_H (128*AS2 + 64*AS2)      // 13824 halfs = 27648 B per stage
#define NSTG  4
#define SMEM_BYTES (NSTG*STG_H*2)     // 110592 B

// ---------------- device scratch ----------------
__device__ __align__(16) float g_WcT[IN_D * MLP_O];
__device__ float g_bc[MLP_O];
__device__ float g_bias0[G4];        // b_ih + b_hh             (t == 0)
__device__ float g_bias1[G4];        // + W_ihA @ bout          (t >= 1)
__device__ __align__(16) __half g_Wph[64 * NCH * 64 * CK];      // packed fp16 weights 10.5MB
__device__ __align__(16) __half g_Ah[(size_t)(SS + 1) * BB * K2]; // [t][b][k] slabs fp16 84.5MB
__device__ __align__(16) float g_c[HH * BB];                    // [j][b]
__device__ unsigned g_cnt = 0;
__device__ unsigned g_gen = 0;

__device__ __forceinline__ uint32_t smem_u32(const void* p)
{
    uint32_t a;
    asm("{ .reg .u64 t; cvta.to.shared.u64 t, %1; cvt.u32.u64 %0, t; }" : "=r"(a) : "l"(p));
    return a;
}

__device__ __forceinline__ void cpasync16(uint32_t dst, const void* src)
{
    asm volatile("cp.async.cg.shared.global [%0], [%1], 16;" :: "r"(dst), "l"(src));
}
#define CP_COMMIT() asm volatile("cp.async.commit_group;")
#define CP_WAIT(N)  asm volatile("cp.async.wait_group %0;" :: "n"(N))

__device__ __forceinline__ void ldsm4(uint32_t r[4], uint32_t addr)
{
    asm volatile("ldmatrix.sync.aligned.m8n8.x4.shared.b16 {%0,%1,%2,%3}, [%4];"
                 : "=r"(r[0]), "=r"(r[1]), "=r"(r[2]), "=r"(r[3]) : "r"(addr));
}

__device__ __forceinline__ void mma_f16(float c[4],
                                        uint32_t a0, uint32_t a1, uint32_t a2, uint32_t a3,
                                        uint32_t b0, uint32_t b1)
{
    asm("mma.sync.aligned.m16n8k16.row.col.f32.f16.f16.f32 "
        "{%0,%1,%2,%3}, {%4,%5,%6,%7}, {%8,%9}, {%0,%1,%2,%3};"
        : "+f"(c[0]), "+f"(c[1]), "+f"(c[2]), "+f"(c[3])
        : "r"(a0), "r"(a1), "r"(a2), "r"(a3), "r"(b0), "r"(b1));
}

// ---------------- grid barrier ----------------
__device__ __forceinline__ void grid_barrier(unsigned &gen)
{
    __syncthreads();
    if (threadIdx.x == 0) {
        __threadfence();
        unsigned ticket = atomicAdd(&g_cnt, 1u);
        if (ticket == NCTA - 1u) {
            g_cnt = 0u;
            __threadfence();
            atomicAdd(&g_gen, 1u);
        } else {
            while (*((volatile unsigned *)&g_gen) == gen) { }
            __threadfence();
        }
    }
    gen += 1u;
    __syncthreads();
}

// ---------------- kernel 0: biases ----------------
__global__ void bias_kernel(const float* __restrict__ W2, const float* __restrict__ b1,
                            const float* __restrict__ b2, const float* __restrict__ bih,
                            const float* __restrict__ bhh, const float* __restrict__ Wih,
                            const float* __restrict__ bout)
{
    int n = blockIdx.x * 256 + threadIdx.x;
    float base = bih[n] + bhh[n];
    float fold = 0.f;
    const float* wa = Wih + n * 320 + 256;
    #pragma unroll
    for (int a = 0; a < 64; a++) fold = fmaf(wa[a], bout[a], fold);
    g_bias0[n] = base;
    g_bias1[n] = base + fold;

    if (blockIdx.x == 0) {
        int tid = threadIdx.x;
        const float* w2r = W2 + tid * 1024;
        float acc = b2[tid];
        #pragma unroll 4
        for (int h = 0; h < 1024; h += 4) {
            float4 w = *(const float4*)(w2r + h);
            acc = fmaf(w.x, b1[h], acc);
            acc = fmaf(w.y, b1[h+1], acc);
            acc = fmaf(w.z, b1[h+2], acc);
            acc = fmaf(w.w, b1[h+3], acc);
        }
        g_bc[tid] = acc;
    }
}

// ---------------- kernel 1: collapse W2@W1 -> WcT[k][o] ----------------
__global__ void collapse_kernel(const float* __restrict__ W1, const float* __restrict__ W2)
{
    __shared__ float w1k[1024];
    int k = blockIdx.x;
    for (int h = threadIdx.x; h < 1024; h += 256) w1k[h] = W1[h * IN_D + k];
    __syncthreads();
    int o = threadIdx.x;
    const float* w2r = W2 + o * 1024;
    float acc = 0.f;
    #pragma unroll 4
    for (int h = 0; h < 1024; h += 4) {
        float4 w = *(const float4*)(w2r + h);
        acc = fmaf(w.x, w1k[h],   acc);
        acc = fmaf(w.y, w1k[h+1], acc);
        acc = fmaf(w.z, w1k[h+2], acc);
        acc = fmaf(w.w, w1k[h+3], acc);
    }
    g_WcT[k * MLP_O + o] = acc;
}

// ---------------- kernel 2: pack fused+folded weights (fp16) ----------------
// g_Wph[jb][ch][col][kk]; col = gate*16 + jl; row = gate*1024 + jb*16 + jl
__global__ void wprep_kernel(const float* __restrict__ Wih, const float* __restrict__ Whh,
                             const float* __restrict__ Wout)
{
    __shared__ float As[64 * 68];       // W_ihA rows for our 64 cols (17.4 KB)
    __shared__ float Wc[64 * 68];       // Wout chunk [a][64 h]      (17.4 KB)
    const int jb  = blockIdx.x;
    const int tid = threadIdx.x;
    __half* wp = g_Wph + (size_t)jb * NCH * (64 * CK);

    // As: [col][a]
    #pragma unroll
    for (int q = 0; q < 16; q++) {
        int idx = q * 256 + tid;
        int col = idx >> 6, a = idx & 63;
        int row = (col >> 4) * 1024 + jb * 16 + (col & 15);
        As[col * 68 + a] = Wih[row * 320 + 256 + a];
    }
    // part 1: k < 256
    #pragma unroll 4
    for (int q = 0; q < 64; q++) {
        int idx = q * 256 + tid;
        int col = idx >> 8, k = idx & 255;
        int row = (col >> 4) * 1024 + jb * 16 + (col & 15);
        wp[(k >> 6) * (64 * CK) + col * CK + (k & 63)] = __float2half(Wih[row * 320 + k]);
    }
    __syncthreads();

    const int col = tid & 63;
    const int hq  = tid >> 6;           // 0..3
    const int row = (col >> 4) * 1024 + jb * 16 + (col & 15);
    for (int hc = 0; hc < 16; hc++) {
        // load Wout chunk: [a 0..63][h 0..63]
        #pragma unroll 4
        for (int q = 0; q < 16; q++) {
            int idx = q * 256 + tid;
            int a = idx >> 6, h = idx & 63;
            Wc[a * 68 + h] = Wout[a * 1024 + hc * 64 + h];
        }
        __syncthreads();
        #pragma unroll 2
        for (int i = 0; i < 16; i++) {
            int h  = hq * 16 + i;
            int hh = hc * 64 + h;
            float fold = 0.f;
            #pragma unroll 8
            for (int a = 0; a < 64; a++)
                fold = fmaf(As[col * 68 + a], Wc[a * 68 + h], fold);
            float val = Whh[row * 1024 + hh] + fold;
            int k = 256 + hh;
            wp[(k >> 6) * (64 * CK) + col * CK + (k & 63)] = __float2half(val);
        }
        __syncthreads();
    }
}

// ---------------- kernel 3: mlp -> g_Ah[s][b][k] (fp16) ----------------
__global__ void mlp_kernel(const float* __restrict__ observe,
                           const float* __restrict__ obstacle,
                           const float* __restrict__ mask)
{
    __shared__ float xs[16 * IN_D];
    __shared__ __half hs[16 * 272];
    const int tid = threadIdx.x;
    const int s   = blockIdx.x >> 4;
    const int b0  = (blockIdx.x & 15) * 16;
    for (int idx = tid; idx < 16 * IN_D; idx += 256) {
        int i = idx / IN_D, k = idx - i * IN_D;
        int p = (b0 + i) * 128 + s;
        float v;
        if (k < 64) v = observe[p * 64 + k];
        else {
            int kk = k - 64;
            v = obstacle[p * 128 + kk] * mask[p * 8 + (kk >> 4)];
        }
        xs[i * IN_D + k] = v;
    }
    __syncthreads();

    float acc[16];
    #pragma unroll
    for (int i = 0; i < 16; i++) acc[i] = 0.f;
    #pragma unroll 4
    for (int k = 0; k < IN_D; k++) {
        float w = g_WcT[k * MLP_O + tid];
        #pragma unroll
        for (int i = 0; i < 16; i++)
            acc[i] = fmaf(xs[i * IN_D + k], w, acc[i]);
    }
    float bcv = g_bc[tid];
    #pragma unroll
    for (int i = 0; i < 16; i++)
        hs[i * 272 + tid] = __float2half(fmaxf(acc[i] + bcv, 0.f));
    __syncthreads();
    int i2 = tid >> 4, seg = tid & 15;
    uint4 v0 = *(uint4*)&hs[i2 * 272 + seg * 16];
    uint4 v1 = *(uint4*)&hs[i2 * 272 + seg * 16 + 8];
    __half* dst = g_Ah + (size_t)s * BB * K2 + (size_t)(b0 + i2) * K2 + seg * 16;
    *(uint4*)dst = v0;
    *(uint4*)(dst + 8) = v1;
}

// ---------------- kernel 4: persistent LSTM (fp16 mma, M=128 N=64 per CTA) ----------------
__global__ void __launch_bounds__(256, 1)
lstm_kernel(int dummy)
{
    extern __shared__ __half smh[];
    float* sg = (float*)smh;                 // epilogue alias [64 col][132]
    __shared__ float sbias[2][64];

    const int tid  = threadIdx.x;
    const int cta  = blockIdx.x;
    const int mh   = cta & 1;                // batch half
    const int jb   = cta >> 1;               // j block (16 j's)
    const int j0   = jb * 16;
    const int lane = tid & 31;
    const int w    = tid >> 5;
    const int wm   = w & 3;                  // M quarter (32 rows)
    const int wn   = w >> 2;                 // N half (32 cols)
    unsigned gen = *((volatile unsigned*)&g_gen);

    const uint32_t sbase = smem_u32(smh);
    const int unit  = tid & 7;
    const int arow0 = tid >> 3;              // 0..31
    const __half* wpk = g_Wph + (size_t)jb * NCH * (64 * CK);

    // ---- init: c = 0, slab0 h-part = 0, sbias ----
    const int gt = cta * 256 + tid;
    for (int i = gt; i < HH * BB; i += NCTA * 256) g_c[i] = 0.f;
    for (int i = gt; i < (HH * BB) / 2; i += NCTA * 256) {
        int b = i >> 9, off = (i & 511) * 2;
        *(uint32_t*)&g_Ah[(size_t)b * K2 + 256 + off] = 0u;
    }
    if (tid < 64) {
        int gate = tid >> 4, jl = tid & 15;
        sbias[0][tid] = g_bias0[gate * 1024 + j0 + jl];
        sbias[1][tid] = g_bias1[gate * 1024 + j0 + jl];
    }
    grid_barrier(gen);

    // ldmatrix per-thread geometry (half offsets)
    const int a_rowoff = (wm * 32 + (lane & 15)) * AS2 + ((lane >> 4) << 3);
    const int b_rowoff = (wn * 32 + (lane & 7) + ((lane >> 4) << 3)) * AS2 + (lane & 8);

    for (int t = 0; t < SS; ++t) {
        const __half* Asl = g_Ah + (size_t)t * BB * K2 + (size_t)mh * 128 * K2;

        float acc[2][4][4];
        #pragma unroll
        for (int mt = 0; mt < 2; mt++)
            #pragma unroll
            for (int nt = 0; nt < 4; nt++)
                #pragma unroll
                for (int r = 0; r < 4; r++) acc[mt][nt][r] = 0.f;

        // prologue: stages 0..2
        #pragma unroll
        for (int s = 0; s < 3; s++) {
            uint32_t sdA = sbase + (s * STG_H) * 2;
            uint32_t sdB = sdA + (128 * AS2) * 2;
            const __half* srcA = Asl + s * CK;
            const __half* srcB = wpk + s * (64 * CK);
            #pragma unroll
            for (int p = 0; p < 4; p++) {
                int br = arow0 + p * 32;
                cpasync16(sdA + (br * AS2 + unit * 8) * 2, srcA + (size_t)br * K2 + unit * 8);
            }
            #pragma unroll
            for (int p = 0; p < 2; p++) {
                int cr = arow0 + p * 32;
                cpasync16(sdB + (cr * AS2 + unit * 8) * 2, srcB + cr * CK + unit * 8);
            }
            CP_COMMIT();
        }

        for (int cc = 0; cc < NCH; cc++) {
            if (cc + 3 < NCH) CP_WAIT(2); else CP_WAIT(0);
            __syncthreads();
            if (cc + 3 < NCH) {
                int s = (cc + 3) & 3;
                uint32_t sdA = sbase + (s * STG_H) * 2;
                uint32_t sdB = sdA + (128 * AS2) * 2;
                const __half* srcA = Asl + (cc + 3) * CK;
                const __half* srcB = wpk + (cc + 3) * (64 * CK);
                #pragma unroll
                for (int p = 0; p < 4; p++) {
                    int br = arow0 + p * 32;
                    cpasync16(sdA + (br * AS2 + unit * 8) * 2, srcA + (size_t)br * K2 + unit * 8);
                }
                #pragma unroll
                for (int p = 0; p < 2; p++) {
                    int cr = arow0 + p * 32;
                    cpasync16(sdB + (cr * AS2 + unit * 8) * 2, srcB + cr * CK + unit * 8);
                }
                CP_COMMIT();
            }
            uint32_t sA_h = sbase + ((cc & 3) * STG_H) * 2;
            uint32_t sB_h = sA_h + (128 * AS2) * 2;
            #pragma unroll
            for (int ks = 0; ks < 4; ks++) {
                const int kk = ks * 16;
                uint32_t af[2][4], bf[2][4];
                ldsm4(af[0], sA_h + (a_rowoff + kk) * 2);
                ldsm4(af[1], sA_h + (a_rowoff + 16 * AS2 + kk) * 2);
                ldsm4(bf[0], sB_h + (b_rowoff + kk) * 2);
                ldsm4(bf[1], sB_h + (b_rowoff + 16 * AS2 + kk) * 2);
                #pragma unroll
                for (int mt = 0; mt < 2; mt++)
                    #pragma unroll
                    for (int nt = 0; nt < 4; nt++)
                        mma_f16(acc[mt][nt],
                                af[mt][0], af[mt][1], af[mt][2], af[mt][3],
                                bf[nt >> 1][(nt & 1) * 2], bf[nt >> 1][(nt & 1) * 2 + 1]);
            }
        }
        __syncthreads();   // stage buffers free -> reuse as sg

        // epilogue: acc -> sg[col][m]
        #pragma unroll
        for (int mt = 0; mt < 2; mt++) {
            int m0 = wm * 32 + mt * 16 + (lane >> 2);
            #pragma unroll
            for (int nt = 0; nt < 4; nt++) {
                int c0 = wn * 32 + nt * 8 + 2 * (lane & 3);
                sg[c0 * 132 + m0]           = acc[mt][nt][0];
                sg[(c0 + 1) * 132 + m0]     = acc[mt][nt][1];
                sg[c0 * 132 + m0 + 8]       = acc[mt][nt][2];
                sg[(c0 + 1) * 132 + m0 + 8] = acc[mt][nt][3];
            }
        }
        __syncthreads();

        // cell update: thread = (b in half, 8 j's)
        {
            const int b  = tid & 127;
            const int js = (tid >> 7) * 8;
            const float* bs = sbias[t > 0 ? 1 : 0];
            __align__(16) __half hbuf[8];
            #pragma unroll
            for (int q = 0; q < 8; q++) {
                int jl = js + q;
                float iv = sg[jl * 132 + b]        + bs[jl];
                float fv = sg[(16 + jl) * 132 + b] + bs[16 + jl];
                float gv = sg[(32 + jl) * 132 + b] + bs[32 + jl];
                float ov = sg[(48 + jl) * 132 + b] + bs[48 + jl];
                iv = 1.f / (1.f + expf(-iv));
                fv = 1.f / (1.f + expf(-fv));
                ov = 1.f / (1.f + expf(-ov));
                gv = tanhf(gv);
                int ci = (j0 + jl) * BB + mh * 128 + b;
                float cnew = fmaf(fv, g_c[ci], iv * gv);
                g_c[ci] = cnew;
                hbuf[q] = __float2half(ov * tanhf(cnew));
            }
            __half* hd = g_Ah + (size_t)(t + 1) * BB * K2
                       + (size_t)(mh * 128 + b) * K2 + 256 + j0 + js;
            *(uint4*)hd = *(uint4*)hbuf;
        }
        grid_barrier(gen);
    }
}

// ---------------- kernel 5: out[b][t][a] = h_t @ Wout^T + bout ----------------
__global__ void finalout_kernel(const float* __restrict__ Wout,
                                const float* __restrict__ bout,
                                float* __restrict__ dout)
{
    __shared__ float sH[128 * 33];      // [b][32 j]
    __shared__ float sWT[32 * 68];      // [j][64 a]
    const int tid = threadIdx.x;
    const int tt  = blockIdx.x >> 1;
    const int b0  = (blockIdx.x & 1) * 128;
    const int b   = tid & 127;
    const int ab  = (tid >> 7) * 32;

    const __half* hsl = g_Ah + (size_t)(tt + 1) * BB * K2;

    float acc[32];
    #pragma unroll
    for (int r = 0; r < 32; r++) acc[r] = 0.f;

    for (int jc = 0; jc < 32; jc++) {
        #pragma unroll
        for (int q = 0; q < 16; q++) {
            int idx = q * 256 + tid;
            int row = idx >> 5, j = idx & 31;
            sH[row * 33 + j] = __half2float(hsl[(size_t)(b0 + row) * K2 + 256 + jc * 32 + j]);
        }
        #pragma unroll
        for (int q = 0; q < 8; q++) {
            int idx = q * 256 + tid;
            int a = idx >> 5, j = idx & 31;
            sWT[j * 68 + a] = Wout[a * 1024 + jc * 32 + j];
        }
        __syncthreads();
        #pragma unroll 4
        for (int k = 0; k < 32; k++) {
            float av = sH[b * 33 + k];
            const float4* wp = (const float4*)(sWT + k * 68 + ab);
            #pragma unroll
            for (int r = 0; r < 8; r++) {
                float4 wv = wp[r];
                acc[r*4+0] = fmaf(av, wv.x, acc[r*4+0]);
                acc[r*4+1] = fmaf(av, wv.y, acc[r*4+1]);
                acc[r*4+2] = fmaf(av, wv.z, acc[r*4+2]);
                acc[r*4+3] = fmaf(av, wv.w, acc[r*4+3]);
            }
        }
        __syncthreads();
    }
    float* dp = dout + (size_t)(b0 + b) * SS * AA + tt * AA + ab;
    #pragma unroll
    for (int r = 0; r < 32; r++) dp[r] = acc[r] + bout[ab + r];
}

// ---------------- launch ----------------
extern "C" void kernel_launch(void* const* d_in, const int* in_sizes, int n_in,
                              void* d_out, int out_size)
{
    const float* observe  = (const float*)d_in[0];
    const float* obstacle = (const float*)d_in[1];
    const float* mask     = (const float*)d_in[2];
    const float* W1       = (const float*)d_in[3];
    const float* b1       = (const float*)d_in[4];
    const float* W2       = (const float*)d_in[5];
    const float* b2       = (const float*)d_in[6];
    const float* W_ih     = (const float*)d_in[7];
    const float* b_ih     = (const float*)d_in[8];
    const float* W_hh     = (const float*)d_in[9];
    const float* b_hh     = (const float*)d_in[10];
    const float* W_out    = (const float*)d_in[11];
    const float* b_out    = (const float*)d_in[12];
    float* out = (float*)d_out;

    cudaFuncSetAttribute(lstm_kernel, cudaFuncAttributeMaxDynamicSharedMemorySize, SMEM_BYTES);

    bias_kernel<<<16, 256>>>(W2, b1, b2, b_ih, b_hh, W_ih, b_out);
    collapse_kernel<<<IN_D, 256>>>(W1, W2);
    wprep_kernel<<<64, 256>>>(W_ih, W_hh, W_out);
    mlp_kernel<<<SS * 16, 256>>>(observe, obstacle, mask);
    lstm_kernel<<<NCTA, 256, SMEM_BYTES>>>(0);
    finalout_kernel<<<SS * 2, 256>>>(W_out, b_out, out);
}

// round 7
// speedup vs baseline: 6.9168x; 1.1766x over previous
#include <cuda_runtime.h>
#include <cuda_fp16.h>
#include <math.h>
#include <stdint.h>

// Problem constants
#define BB    256
#define SS    128
#define IN_D  192
#define MLP_O 256
#define HH    1024
#define AA    64
#define K2    1280          // MLP_O + HH (o_prev folded away)
#define CK    64            // K per chunk
#define NCH   20            // K2/CK  (chunks 0..3 = mlp part, 4..19 = h part)
#define G4    4096
#define NCTA  128

// lstm smem geometry (halfs) — W persistent + 3 swizzled A stages
#define W_HALFS  (NCH * 64 * CK)       // 81920 halfs = 160 KB
#define ASTG_H   (128 * CK)            // 8192 halfs  = 16 KB per stage
#define NSTG     3
#define SMEM_BYTES ((W_HALFS + NSTG * ASTG_H) * 2)   // 212992 B

// ---------------- device scratch ----------------
__device__ __align__(16) float g_WcT[IN_D * MLP_O];
__device__ float g_bc[MLP_O];
__device__ float g_bias0[G4];        // b_ih + b_hh             (t == 0)
__device__ float g_bias1[G4];        // + W_ihA @ bout          (t >= 1)
__device__ __align__(16) __half g_Wph[64 * W_HALFS];              // packed swizzled fp16 W
__device__ __align__(16) __half g_Ah[(size_t)(SS + 1) * BB * K2]; // [t][b][k] slabs fp16
__device__ __align__(16) float g_c[HH * BB];                      // [j][b]
__device__ unsigned g_cnt = 0;
__device__ unsigned g_gen = 0;

__device__ __forceinline__ uint32_t smem_u32(const void* p)
{
    uint32_t a;
    asm("{ .reg .u64 t; cvta.to.shared.u64 t, %1; cvt.u32.u64 %0, t; }" : "=r"(a) : "l"(p));
    return a;
}

__device__ __forceinline__ void cpasync16(uint32_t dst, const void* src)
{
    asm volatile("cp.async.cg.shared.global [%0], [%1], 16;" :: "r"(dst), "l"(src));
}
#define CP_COMMIT() asm volatile("cp.async.commit_group;")
#define CP_WAIT(N)  asm volatile("cp.async.wait_group %0;" :: "n"(N))

__device__ __forceinline__ void ldsm4(uint32_t r[4], uint32_t addr)
{
    asm volatile("ldmatrix.sync.aligned.m8n8.x4.shared.b16 {%0,%1,%2,%3}, [%4];"
                 : "=r"(r[0]), "=r"(r[1]), "=r"(r[2]), "=r"(r[3]) : "r"(addr));
}

__device__ __forceinline__ void mma_f16(float c[4],
                                        uint32_t a0, uint32_t a1, uint32_t a2, uint32_t a3,
                                        uint32_t b0, uint32_t b1)
{
    asm("mma.sync.aligned.m16n8k16.row.col.f32.f16.f16.f32 "
        "{%0,%1,%2,%3}, {%4,%5,%6,%7}, {%8,%9}, {%0,%1,%2,%3};"
        : "+f"(c[0]), "+f"(c[1]), "+f"(c[2]), "+f"(c[3])
        : "r"(a0), "r"(a1), "r"(a2), "r"(a3), "r"(b0), "r"(b1));
}

// ---------------- full grid barrier (init only) ----------------
__device__ __forceinline__ void grid_barrier(unsigned &gen)
{
    __syncthreads();
    if (threadIdx.x == 0) {
        __threadfence();
        unsigned ticket = atomicAdd(&g_cnt, 1u);
        if (ticket == NCTA - 1u) {
            g_cnt = 0u;
            __threadfence();
            atomicAdd(&g_gen, 1u);
        } else {
            while (*((volatile unsigned *)&g_gen) == gen) { }
            __threadfence();
        }
    }
    gen += 1u;
    __syncthreads();
}

// ---------------- kernel 0: biases ----------------
__global__ void bias_kernel(const float* __restrict__ W2, const float* __restrict__ b1,
                            const float* __restrict__ b2, const float* __restrict__ bih,
                            const float* __restrict__ bhh, const float* __restrict__ Wih,
                            const float* __restrict__ bout)
{
    int n = blockIdx.x * 256 + threadIdx.x;
    float base = bih[n] + bhh[n];
    float fold = 0.f;
    const float* wa = Wih + n * 320 + 256;
    #pragma unroll
    for (int a = 0; a < 64; a++) fold = fmaf(wa[a], bout[a], fold);
    g_bias0[n] = base;
    g_bias1[n] = base + fold;

    if (blockIdx.x == 0) {
        int tid = threadIdx.x;
        const float* w2r = W2 + tid * 1024;
        float acc = b2[tid];
        #pragma unroll 4
        for (int h = 0; h < 1024; h += 4) {
            float4 w = *(const float4*)(w2r + h);
            acc = fmaf(w.x, b1[h], acc);
            acc = fmaf(w.y, b1[h+1], acc);
            acc = fmaf(w.z, b1[h+2], acc);
            acc = fmaf(w.w, b1[h+3], acc);
        }
        g_bc[tid] = acc;
    }
}

// ---------------- kernel 1: collapse W2@W1 -> WcT[k][o] ----------------
__global__ void collapse_kernel(const float* __restrict__ W1, const float* __restrict__ W2)
{
    __shared__ float w1k[1024];
    int k = blockIdx.x;
    for (int h = threadIdx.x; h < 1024; h += 256) w1k[h] = W1[h * IN_D + k];
    __syncthreads();
    int o = threadIdx.x;
    const float* w2r = W2 + o * 1024;
    float acc = 0.f;
    #pragma unroll 4
    for (int h = 0; h < 1024; h += 4) {
        float4 w = *(const float4*)(w2r + h);
        acc = fmaf(w.x, w1k[h],   acc);
        acc = fmaf(w.y, w1k[h+1], acc);
        acc = fmaf(w.z, w1k[h+2], acc);
        acc = fmaf(w.w, w1k[h+3], acc);
    }
    g_WcT[k * MLP_O + o] = acc;
}

// ---------------- kernel 2: pack fused+folded weights (fp16, swizzled smem image) ----------------
// element (col,k): chunk=k>>6, unit=(k>>3)&7, sw_unit=unit^(col&7)
// idx = chunk*4096 + col*64 + sw_unit*8 + (k&7)
__global__ void wprep_kernel(const float* __restrict__ Wih, const float* __restrict__ Whh,
                             const float* __restrict__ Wout)
{
    __shared__ float As[64 * 68];
    __shared__ float Wc[64 * 68];
    const int jb  = blockIdx.x;
    const int tid = threadIdx.x;
    __half* wp = g_Wph + (size_t)jb * W_HALFS;

    #pragma unroll
    for (int q = 0; q < 16; q++) {
        int idx = q * 256 + tid;
        int col = idx >> 6, a = idx & 63;
        int row = (col >> 4) * 1024 + jb * 16 + (col & 15);
        As[col * 68 + a] = Wih[row * 320 + 256 + a];
    }
    // part 1: k < 256
    #pragma unroll 4
    for (int q = 0; q < 64; q++) {
        int idx = q * 256 + tid;
        int col = idx >> 8, k = idx & 255;
        int row = (col >> 4) * 1024 + jb * 16 + (col & 15);
        int sw  = ((k >> 3) & 7) ^ (col & 7);
        wp[(k >> 6) * 4096 + col * 64 + sw * 8 + (k & 7)] = __float2half(Wih[row * 320 + k]);
    }
    __syncthreads();

    const int col = tid & 63;
    const int hq  = tid >> 6;
    const int row = (col >> 4) * 1024 + jb * 16 + (col & 15);
    for (int hc = 0; hc < 16; hc++) {
        #pragma unroll 4
        for (int q = 0; q < 16; q++) {
            int idx = q * 256 + tid;
            int a = idx >> 6, h = idx & 63;
            Wc[a * 68 + h] = Wout[a * 1024 + hc * 64 + h];
        }
        __syncthreads();
        #pragma unroll 2
        for (int i = 0; i < 16; i++) {
            int h  = hq * 16 + i;
            int hh = hc * 64 + h;
            float fold = 0.f;
            #pragma unroll 8
            for (int a = 0; a < 64; a++)
                fold = fmaf(As[col * 68 + a], Wc[a * 68 + h], fold);
            float val = Whh[row * 1024 + hh] + fold;
            int k = 256 + hh;
            int sw = ((k >> 3) & 7) ^ (col & 7);
            wp[(k >> 6) * 4096 + col * 64 + sw * 8 + (k & 7)] = __float2half(val);
        }
        __syncthreads();
    }
}

// ---------------- kernel 3: mlp -> g_Ah[s][b][k] (fp16) ----------------
__global__ void mlp_kernel(const float* __restrict__ observe,
                           const float* __restrict__ obstacle,
                           const float* __restrict__ mask)
{
    __shared__ float xs[16 * IN_D];
    __shared__ __half hs[16 * 272];
    const int tid = threadIdx.x;
    const int s   = blockIdx.x >> 4;
    const int b0  = (blockIdx.x & 15) * 16;
    for (int idx = tid; idx < 16 * IN_D; idx += 256) {
        int i = idx / IN_D, k = idx - i * IN_D;
        int p = (b0 + i) * 128 + s;
        float v;
        if (k < 64) v = observe[p * 64 + k];
        else {
            int kk = k - 64;
            v = obstacle[p * 128 + kk] * mask[p * 8 + (kk >> 4)];
        }
        xs[i * IN_D + k] = v;
    }
    __syncthreads();

    float acc[16];
    #pragma unroll
    for (int i = 0; i < 16; i++) acc[i] = 0.f;
    #pragma unroll 4
    for (int k = 0; k < IN_D; k++) {
        float w = g_WcT[k * MLP_O + tid];
        #pragma unroll
        for (int i = 0; i < 16; i++)
            acc[i] = fmaf(xs[i * IN_D + k], w, acc[i]);
    }
    float bcv = g_bc[tid];
    #pragma unroll
    for (int i = 0; i < 16; i++)
        hs[i * 272 + tid] = __float2half(fmaxf(acc[i] + bcv, 0.f));
    __syncthreads();
    int i2 = tid >> 4, seg = tid & 15;
    uint4 v0 = *(uint4*)&hs[i2 * 272 + seg * 16];
    uint4 v1 = *(uint4*)&hs[i2 * 272 + seg * 16 + 8];
    __half* dst = g_Ah + (size_t)s * BB * K2 + (size_t)(b0 + i2) * K2 + seg * 16;
    *(uint4*)dst = v0;
    *(uint4*)(dst + 8) = v1;
}

// ---------------- kernel 4: persistent LSTM ----------------
__global__ void __launch_bounds__(256, 1)
lstm_kernel(int dummy)
{
    extern __shared__ __half smh[];
    float* sg = (float*)(smh + W_HALFS);     // epilogue alias of A stages
    __shared__ float sbias[2][64];

    const int tid  = threadIdx.x;
    const int cta  = blockIdx.x;
    const int mh   = cta & 1;                // batch half
    const int jb   = cta >> 1;               // j block (16 j's)
    const int j0   = jb * 16;
    const int lane = tid & 31;
    const int w    = tid >> 5;
    const int wm   = w & 3;                  // M quarter (32 rows)
    const int wn   = w >> 2;                 // N half (32 cols)
    unsigned gen = *((volatile unsigned*)&g_gen);

    const uint32_t sbase = smem_u32(smh);
    const uint32_t wbase = sbase;
    const uint32_t abase = sbase + W_HALFS * 2;
    const int arow  = tid >> 3;              // 0..31
    const int aunit = tid & 7;

    // ---- load persistent W (swizzled image, straight copy) ----
    {
        const __half* src = g_Wph + (size_t)jb * W_HALFS;
        for (int u = tid; u < W_HALFS / 8; u += 256)
            cpasync16(wbase + u * 16, src + (size_t)u * 8);
        CP_COMMIT();
    }

    // ---- init: c = 0, slab0 h-part = 0, sbias ----
    const int gt = cta * 256 + tid;
    for (int i = gt; i < HH * BB; i += NCTA * 256) g_c[i] = 0.f;
    for (int i = gt; i < (HH * BB) / 2; i += NCTA * 256) {
        int b = i >> 9, off = (i & 511) * 2;
        *(uint32_t*)&g_Ah[(size_t)b * K2 + 256 + off] = 0u;
    }
    if (tid < 64) {
        int gate = tid >> 4, jl = tid & 15;
        sbias[0][tid] = g_bias0[gate * 1024 + j0 + jl];
        sbias[1][tid] = g_bias1[gate * 1024 + j0 + jl];
    }
    CP_WAIT(0);
    grid_barrier(gen);

    // A prefetch: chunk cc of slab -> stage cc%3 (swizzled)
    auto prefA = [&](const __half* Asl, int cc) {
        uint32_t sd = abase + ((cc % 3) * ASTG_H) * 2;
        const __half* src = Asl + cc * CK + aunit * 8;
        #pragma unroll
        for (int p = 0; p < 4; p++) {
            int r = arow + p * 32;
            cpasync16(sd + r * 128 + ((aunit ^ (r & 7)) << 4), src + (size_t)r * K2);
        }
        CP_COMMIT();
    };

    // one K=64 chunk of mma work from stage (cc%3) + persistent W chunk cc
    auto do_chunk = [&](int cc, float (&acc)[2][4][4]) {
        uint32_t sA = abase + ((cc % 3) * ASTG_H) * 2;
        uint32_t sB = wbase + cc * 8192;
        #pragma unroll
        for (int ks = 0; ks < 4; ks++) {
            const int ku0 = ks * 2;
            uint32_t af[2][4], bf[2][4];
            #pragma unroll
            for (int mt = 0; mt < 2; mt++) {
                int m  = wm * 32 + mt * 16 + (lane & 15);
                int ku = (lane >> 4) + ku0;
                ldsm4(af[mt], sA + m * 128 + ((ku ^ (m & 7)) << 4));
            }
            #pragma unroll
            for (int nh = 0; nh < 2; nh++) {
                int n  = wn * 32 + nh * 16 + (lane & 7) + ((lane >> 4) << 3);
                int ku = ((lane & 8) >> 3) + ku0;
                ldsm4(bf[nh], sB + n * 128 + ((ku ^ (n & 7)) << 4));
            }
            #pragma unroll
            for (int mt = 0; mt < 2; mt++)
                #pragma unroll
                for (int nt = 0; nt < 4; nt++)
                    mma_f16(acc[mt][nt],
                            af[mt][0], af[mt][1], af[mt][2], af[mt][3],
                            bf[nt >> 1][(nt & 1) * 2], bf[nt >> 1][(nt & 1) * 2 + 1]);
        }
    };

    // prime: slab0 chunks 0,1
    prefA(g_Ah + (size_t)mh * 128 * K2, 0);
    prefA(g_Ah + (size_t)mh * 128 * K2, 1);

    for (int t = 0; t < SS; ++t) {
        const __half* Asl = g_Ah + (size_t)t * BB * K2 + (size_t)mh * 128 * K2;

        float acc[2][4][4];
        #pragma unroll
        for (int mt = 0; mt < 2; mt++)
            #pragma unroll
            for (int nt = 0; nt < 4; nt++)
                #pragma unroll
                for (int r = 0; r < 4; r++) acc[mt][nt][r] = 0.f;

        // ---- pre-wait region: mlp chunks 0..3 (independent of other CTAs) ----
        for (int cc = 0; cc < 4; cc++) {
            if (cc < 3) { CP_WAIT(1); } else { CP_WAIT(0); }
            __syncthreads();
            if (cc + 2 <= 3) prefA(Asl, cc + 2);
            do_chunk(cc, acc);
        }

        // ---- barrier wait (arrive happened at end of previous step) ----
        if (t > 0) {
            if (tid == 0) {
                while (*((volatile unsigned*)&g_gen) == gen) { }
                __threadfence();
            }
            gen += 1u;
        }
        __syncthreads();

        // ---- h chunks 4..19 ----
        prefA(Asl, 4);
        prefA(Asl, 5);
        for (int cc = 4; cc < NCH; cc++) {
            if (cc < NCH - 1) { CP_WAIT(1); } else { CP_WAIT(0); }
            __syncthreads();
            if (cc + 2 < NCH) prefA(Asl, cc + 2);
            do_chunk(cc, acc);
        }
        __syncthreads();   // stages free -> reuse as sg

        // ---- epilogue: acc -> sg[col][m] ----
        #pragma unroll
        for (int mt = 0; mt < 2; mt++) {
            int m0 = wm * 32 + mt * 16 + (lane >> 2);
            #pragma unroll
            for (int nt = 0; nt < 4; nt++) {
                int c0 = wn * 32 + nt * 8 + 2 * (lane & 3);
                sg[c0 * 132 + m0]           = acc[mt][nt][0];
                sg[(c0 + 1) * 132 + m0]     = acc[mt][nt][1];
                sg[c0 * 132 + m0 + 8]       = acc[mt][nt][2];
                sg[(c0 + 1) * 132 + m0 + 8] = acc[mt][nt][3];
            }
        }
        __syncthreads();

        // ---- cell update ----
        {
            const int b  = tid & 127;
            const int js = (tid >> 7) * 8;
            const float* bs = sbias[t > 0 ? 1 : 0];
            __align__(16) __half hbuf[8];
            #pragma unroll
            for (int q = 0; q < 8; q++) {
                int jl = js + q;
                float iv = sg[jl * 132 + b]        + bs[jl];
                float fv = sg[(16 + jl) * 132 + b] + bs[16 + jl];
                float gv = sg[(32 + jl) * 132 + b] + bs[32 + jl];
                float ov = sg[(48 + jl) * 132 + b] + bs[48 + jl];
                iv = 1.f / (1.f + expf(-iv));
                fv = 1.f / (1.f + expf(-fv));
                ov = 1.f / (1.f + expf(-ov));
                gv = tanhf(gv);
                int ci = (j0 + jl) * BB + mh * 128 + b;
                float cnew = fmaf(fv, g_c[ci], iv * gv);
                g_c[ci] = cnew;
                hbuf[q] = __float2half(ov * tanhf(cnew));
            }
            __half* hd = g_Ah + (size_t)(t + 1) * BB * K2
                       + (size_t)(mh * 128 + b) * K2 + 256 + j0 + js;
            *(uint4*)hd = *(uint4*)hbuf;
        }
        __syncthreads();   // sg reads done before stages reused

        // ---- split-barrier arrive + prefetch next-step mlp chunks ----
        if (t + 1 < SS) {
            if (tid == 0) {
                __threadfence();
                unsigned ticket = atomicAdd(&g_cnt, 1u);
                if (ticket == NCTA - 1u) {
                    g_cnt = 0u;
                    __threadfence();
                    atomicAdd(&g_gen, 1u);
                }
            }
            const __half* AslN = Asl + (size_t)BB * K2;
            prefA(AslN, 0);
            prefA(AslN, 1);
        }
    }
}

// ---------------- kernel 5: out[b][t][a] = h_t @ Wout^T + bout ----------------
__global__ void finalout_kernel(const float* __restrict__ Wout,
                                const float* __restrict__ bout,
                                float* __restrict__ dout)
{
    __shared__ float sH[128 * 33];
    __shared__ float sWT[32 * 68];
    const int tid = threadIdx.x;
    const int tt  = blockIdx.x >> 1;
    const int b0  = (blockIdx.x & 1) * 128;
    const int b   = tid & 127;
    const int ab  = (tid >> 7) * 32;

    const __half* hsl = g_Ah + (size_t)(tt + 1) * BB * K2;

    float acc[32];
    #pragma unroll
    for (int r = 0; r < 32; r++) acc[r] = 0.f;

    for (int jc = 0; jc < 32; jc++) {
        #pragma unroll
        for (int q = 0; q < 16; q++) {
            int idx = q * 256 + tid;
            int row = idx >> 5, j = idx & 31;
            sH[row * 33 + j] = __half2float(hsl[(size_t)(b0 + row) * K2 + 256 + jc * 32 + j]);
        }
        #pragma unroll
        for (int q = 0; q < 8; q++) {
            int idx = q * 256 + tid;
            int a = idx >> 5, j = idx & 31;
            sWT[j * 68 + a] = Wout[a * 1024 + jc * 32 + j];
        }
        __syncthreads();
        #pragma unroll 4
        for (int k = 0; k < 32; k++) {
            float av = sH[b * 33 + k];
            const float4* wp = (const float4*)(sWT + k * 68 + ab);
            #pragma unroll
            for (int r = 0; r < 8; r++) {
                float4 wv = wp[r];
                acc[r*4+0] = fmaf(av, wv.x, acc[r*4+0]);
                acc[r*4+1] = fmaf(av, wv.y, acc[r*4+1]);
                acc[r*4+2] = fmaf(av, wv.z, acc[r*4+2]);
                acc[r*4+3] = fmaf(av, wv.w, acc[r*4+3]);
            }
        }
        __syncthreads();
    }
    float* dp = dout + (size_t)(b0 + b) * SS * AA + tt * AA + ab;
    #pragma unroll
    for (int r = 0; r < 32; r++) dp[r] = acc[r] + bout[ab + r];
}

// ---------------- launch ----------------
extern "C" void kernel_launch(void* const* d_in, const int* in_sizes, int n_in,
                              void* d_out, int out_size)
{
    const float* observe  = (const float*)d_in[0];
    const float* obstacle = (const float*)d_in[1];
    const float* mask     = (const float*)d_in[2];
    const float* W1       = (const float*)d_in[3];
    const float* b1       = (const float*)d_in[4];
    const float* W2       = (const float*)d_in[5];
    const float* b2       = (const float*)d_in[6];
    const float* W_ih     = (const float*)d_in[7];
    const float* b_ih     = (const float*)d_in[8];
    const float* W_hh     = (const float*)d_in[9];
    const float* b_hh     = (const float*)d_in[10];
    const float* W_out    = (const float*)d_in[11];
    const float* b_out    = (const float*)d_in[12];
    float* out = (float*)d_out;

    cudaFuncSetAttribute(lstm_kernel, cudaFuncAttributeMaxDynamicSharedMemorySize, SMEM_BYTES);

    bias_kernel<<<16, 256>>>(W2, b1, b2, b_ih, b_hh, W_ih, b_out);
    collapse_kernel<<<IN_D, 256>>>(W1, W2);
    wprep_kernel<<<64, 256>>>(W_ih, W_hh, W_out);
    mlp_kernel<<<SS * 16, 256>>>(observe, obstacle, mask);
    lstm_kernel<<<NCTA, 256, SMEM_BYTES>>>(0);
    finalout_kernel<<<SS * 2, 256>>>(W_out, b_out, out);
}

// round 8
// speedup vs baseline: 7.4645x; 1.0792x over previous
#include <cuda_runtime.h>
#include <cuda_fp16.h>
#include <math.h>
#include <stdint.h>

// Problem constants
#define BB    256
#define SS    128
#define IN_D  192
#define MLP_O 256
#define HH    1024
#define AA    64
#define K2    1280          // MLP_O + HH (o_prev folded away)
#define CK    64            // K per chunk
#define NCH   20            // K2/CK  (chunks 0..3 = mlp part, 4..19 = h part)
#define G4    4096
#define NCTA  128

// lstm smem geometry (halfs) — W persistent + per-pair swizzled A stages
#define W_HALFS  (NCH * 64 * CK)       // 81920 halfs = 160 KB
#define ASTG2_B  4096                  // bytes per pair stage (32 rows x 64 halfs)
#define NSTG     3
#define A_HALFS  (4 * NSTG * (ASTG2_B / 2))              // 24576 halfs = 48 KB
#define SMEM_BYTES ((W_HALFS + A_HALFS) * 2)             // 212992 B

// ---------------- device scratch ----------------
__device__ __align__(16) float g_WcT[IN_D * MLP_O];
__device__ float g_bc[MLP_O];
__device__ float g_bias0[G4];        // b_ih + b_hh             (t == 0)
__device__ float g_bias1[G4];        // + W_ihA @ bout          (t >= 1)
__device__ __align__(16) __half g_Wph[64 * W_HALFS];              // packed swizzled fp16 W
__device__ __align__(16) __half g_Ah[(size_t)(SS + 1) * BB * K2]; // [t][b][k] slabs fp16
__device__ __align__(16) float g_c[HH * BB];                      // [j][b]
__device__ unsigned g_cnt = 0;
__device__ unsigned g_gen = 0;

__device__ __forceinline__ uint32_t smem_u32(const void* p)
{
    uint32_t a;
    asm("{ .reg .u64 t; cvta.to.shared.u64 t, %1; cvt.u32.u64 %0, t; }" : "=r"(a) : "l"(p));
    return a;
}

__device__ __forceinline__ void cpasync16(uint32_t dst, const void* src)
{
    asm volatile("cp.async.cg.shared.global [%0], [%1], 16;" :: "r"(dst), "l"(src));
}
#define CP_COMMIT() asm volatile("cp.async.commit_group;")
#define CP_WAIT(N)  asm volatile("cp.async.wait_group %0;" :: "n"(N))

__device__ __forceinline__ void ldsm4(uint32_t r[4], uint32_t addr)
{
    asm volatile("ldmatrix.sync.aligned.m8n8.x4.shared.b16 {%0,%1,%2,%3}, [%4];"
                 : "=r"(r[0]), "=r"(r[1]), "=r"(r[2]), "=r"(r[3]) : "r"(addr));
}

__device__ __forceinline__ void mma_f16(float c[4],
                                        uint32_t a0, uint32_t a1, uint32_t a2, uint32_t a3,
                                        uint32_t b0, uint32_t b1)
{
    asm("mma.sync.aligned.m16n8k16.row.col.f32.f16.f16.f32 "
        "{%0,%1,%2,%3}, {%4,%5,%6,%7}, {%8,%9}, {%0,%1,%2,%3};"
        : "+f"(c[0]), "+f"(c[1]), "+f"(c[2]), "+f"(c[3])
        : "r"(a0), "r"(a1), "r"(a2), "r"(a3), "r"(b0), "r"(b1));
}

// ---------------- full grid barrier (init only) ----------------
__device__ __forceinline__ void grid_barrier(unsigned &gen)
{
    __syncthreads();
    if (threadIdx.x == 0) {
        __threadfence();
        unsigned ticket = atomicAdd(&g_cnt, 1u);
        if (ticket == NCTA - 1u) {
            g_cnt = 0u;
            __threadfence();
            atomicAdd(&g_gen, 1u);
        } else {
            while (*((volatile unsigned *)&g_gen) == gen) { }
            __threadfence();
        }
    }
    gen += 1u;
    __syncthreads();
}

// ---------------- kernel 0: biases ----------------
__global__ void bias_kernel(const float* __restrict__ W2, const float* __restrict__ b1,
                            const float* __restrict__ b2, const float* __restrict__ bih,
                            const float* __restrict__ bhh, const float* __restrict__ Wih,
                            const float* __restrict__ bout)
{
    int n = blockIdx.x * 256 + threadIdx.x;
    float base = bih[n] + bhh[n];
    float fold = 0.f;
    const float* wa = Wih + n * 320 + 256;
    #pragma unroll
    for (int a = 0; a < 64; a++) fold = fmaf(wa[a], bout[a], fold);
    g_bias0[n] = base;
    g_bias1[n] = base + fold;

    if (blockIdx.x == 0) {
        int tid = threadIdx.x;
        const float* w2r = W2 + tid * 1024;
        float acc = b2[tid];
        #pragma unroll 4
        for (int h = 0; h < 1024; h += 4) {
            float4 w = *(const float4*)(w2r + h);
            acc = fmaf(w.x, b1[h], acc);
            acc = fmaf(w.y, b1[h+1], acc);
            acc = fmaf(w.z, b1[h+2], acc);
            acc = fmaf(w.w, b1[h+3], acc);
        }
        g_bc[tid] = acc;
    }
}

// ---------------- kernel 1: collapse W2@W1 -> WcT[k][o] ----------------
__global__ void collapse_kernel(const float* __restrict__ W1, const float* __restrict__ W2)
{
    __shared__ float w1k[1024];
    int k = blockIdx.x;
    for (int h = threadIdx.x; h < 1024; h += 256) w1k[h] = W1[h * IN_D + k];
    __syncthreads();
    int o = threadIdx.x;
    const float* w2r = W2 + o * 1024;
    float acc = 0.f;
    #pragma unroll 4
    for (int h = 0; h < 1024; h += 4) {
        float4 w = *(const float4*)(w2r + h);
        acc = fmaf(w.x, w1k[h],   acc);
        acc = fmaf(w.y, w1k[h+1], acc);
        acc = fmaf(w.z, w1k[h+2], acc);
        acc = fmaf(w.w, w1k[h+3], acc);
    }
    g_WcT[k * MLP_O + o] = acc;
}

// ---------------- kernel 2: pack fused+folded weights (fp16, swizzled smem image) ----------------
__global__ void wprep_kernel(const float* __restrict__ Wih, const float* __restrict__ Whh,
                             const float* __restrict__ Wout)
{
    __shared__ float As[64 * 68];
    __shared__ float Wc[64 * 68];
    const int jb  = blockIdx.x;
    const int tid = threadIdx.x;
    __half* wp = g_Wph + (size_t)jb * W_HALFS;

    #pragma unroll
    for (int q = 0; q < 16; q++) {
        int idx = q * 256 + tid;
        int col = idx >> 6, a = idx & 63;
        int row = (col >> 4) * 1024 + jb * 16 + (col & 15);
        As[col * 68 + a] = Wih[row * 320 + 256 + a];
    }
    // part 1: k < 256
    #pragma unroll 4
    for (int q = 0; q < 64; q++) {
        int idx = q * 256 + tid;
        int col = idx >> 8, k = idx & 255;
        int row = (col >> 4) * 1024 + jb * 16 + (col & 15);
        int sw  = ((k >> 3) & 7) ^ (col & 7);
        wp[(k >> 6) * 4096 + col * 64 + sw * 8 + (k & 7)] = __float2half(Wih[row * 320 + k]);
    }
    __syncthreads();

    const int col = tid & 63;
    const int hq  = tid >> 6;
    const int row = (col >> 4) * 1024 + jb * 16 + (col & 15);
    for (int hc = 0; hc < 16; hc++) {
        #pragma unroll 4
        for (int q = 0; q < 16; q++) {
            int idx = q * 256 + tid;
            int a = idx >> 6, h = idx & 63;
            Wc[a * 68 + h] = Wout[a * 1024 + hc * 64 + h];
        }
        __syncthreads();
        #pragma unroll 2
        for (int i = 0; i < 16; i++) {
            int h  = hq * 16 + i;
            int hh = hc * 64 + h;
            float fold = 0.f;
            #pragma unroll 8
            for (int a = 0; a < 64; a++)
                fold = fmaf(As[col * 68 + a], Wc[a * 68 + h], fold);
            float val = Whh[row * 1024 + hh] + fold;
            int k = 256 + hh;
            int sw = ((k >> 3) & 7) ^ (col & 7);
            wp[(k >> 6) * 4096 + col * 64 + sw * 8 + (k & 7)] = __float2half(val);
        }
        __syncthreads();
    }
}

// ---------------- kernel 3: mlp -> g_Ah[s][b][k] (fp16) ----------------
__global__ void mlp_kernel(const float* __restrict__ observe,
                           const float* __restrict__ obstacle,
                           const float* __restrict__ mask)
{
    __shared__ float xs[16 * IN_D];
    __shared__ __half hs[16 * 272];
    const int tid = threadIdx.x;
    const int s   = blockIdx.x >> 4;
    const int b0  = (blockIdx.x & 15) * 16;
    for (int idx = tid; idx < 16 * IN_D; idx += 256) {
        int i = idx / IN_D, k = idx - i * IN_D;
        int p = (b0 + i) * 128 + s;
        float v;
        if (k < 64) v = observe[p * 64 + k];
        else {
            int kk = k - 64;
            v = obstacle[p * 128 + kk] * mask[p * 8 + (kk >> 4)];
        }
        xs[i * IN_D + k] = v;
    }
    __syncthreads();

    float acc[16];
    #pragma unroll
    for (int i = 0; i < 16; i++) acc[i] = 0.f;
    #pragma unroll 4
    for (int k = 0; k < IN_D; k++) {
        float w = g_WcT[k * MLP_O + tid];
        #pragma unroll
        for (int i = 0; i < 16; i++)
            acc[i] = fmaf(xs[i * IN_D + k], w, acc[i]);
    }
    float bcv = g_bc[tid];
    #pragma unroll
    for (int i = 0; i < 16; i++)
        hs[i * 272 + tid] = __float2half(fmaxf(acc[i] + bcv, 0.f));
    __syncthreads();
    int i2 = tid >> 4, seg = tid & 15;
    uint4 v0 = *(uint4*)&hs[i2 * 272 + seg * 16];
    uint4 v1 = *(uint4*)&hs[i2 * 272 + seg * 16 + 8];
    __half* dst = g_Ah + (size_t)s * BB * K2 + (size_t)(b0 + i2) * K2 + seg * 16;
    *(uint4*)dst = v0;
    *(uint4*)(dst + 8) = v1;
}

// ---------------- kernel 4: persistent LSTM (warp-pair pipelines) ----------------
__global__ void __launch_bounds__(256, 1)
lstm_kernel(int dummy)
{
    extern __shared__ __half smh[];
    float* sg = (float*)(smh + W_HALFS);     // epilogue alias of A stage region
    __shared__ float sbias[2][64];

    const int tid  = threadIdx.x;
    const int cta  = blockIdx.x;
    const int mh   = cta & 1;                // batch half
    const int jb   = cta >> 1;               // j block (16 j's)
    const int j0   = jb * 16;
    const int lane = tid & 31;
    const int w    = tid >> 5;
    const int wm   = w & 3;                  // M quarter (32 rows) == pair id
    const int wn   = w >> 2;                 // N half (32 cols)
    unsigned gen = *((volatile unsigned*)&g_gen);

    const uint32_t sbase = smem_u32(smh);
    const uint32_t wbase = sbase;
    const uint32_t abase = sbase + W_HALFS * 2;

    // ---- load persistent W (swizzled image, straight copy) ----
    {
        const __half* src = g_Wph + (size_t)jb * W_HALFS;
        for (int u = tid; u < W_HALFS / 8; u += 256)
            cpasync16(wbase + u * 16, src + (size_t)u * 8);
        CP_COMMIT();
    }

    // ---- init: c = 0, slab0 h-part = 0, sbias ----
    const int gt = cta * 256 + tid;
    for (int i = gt; i < HH * BB; i += NCTA * 256) g_c[i] = 0.f;
    for (int i = gt; i < (HH * BB) / 2; i += NCTA * 256) {
        int b = i >> 9, off = (i & 511) * 2;
        *(uint32_t*)&g_Ah[(size_t)b * K2 + 256 + off] = 0u;
    }
    if (tid < 64) {
        int gate = tid >> 4, jl = tid & 15;
        sbias[0][tid] = g_bias0[gate * 1024 + j0 + jl];
        sbias[1][tid] = g_bias1[gate * 1024 + j0 + jl];
    }
    CP_WAIT(0);
    grid_barrier(gen);

    // pair barrier: warps {wm, wm+4}, 64 threads, named barrier wm+1
    #define BAR_PAIR() asm volatile("bar.sync %0, %1;" :: "r"(wm + 1), "r"(64) : "memory")

    // pair A prefetch: both warps of the pair load half the 4KB sub-tile
    auto prefA = [&](const __half* Asl, int cc) {
        uint32_t sd = abase + (wm * NSTG + (cc % 3)) * ASTG2_B;
        const __half* src = Asl + (size_t)(wm * 32) * K2 + cc * CK;
        #pragma unroll
        for (int i = 0; i < 4; i++) {
            int idx = i * 64 + wn * 32 + lane;      // 0..255 unit id
            int r = idx >> 3, u = idx & 7;
            cpasync16(sd + r * 128 + ((u ^ (r & 7)) << 4), src + (size_t)r * K2 + u * 8);
        }
        CP_COMMIT();
    };

    // one K=64 chunk: pair stage (cc%3) + persistent W chunk cc
    auto do_chunk = [&](int cc, float (&acc)[2][4][4]) {
        uint32_t sA = abase + (wm * NSTG + (cc % 3)) * ASTG2_B;
        uint32_t sB = wbase + cc * 8192;
        #pragma unroll
        for (int ks = 0; ks < 4; ks++) {
            const int ku0 = ks * 2;
            uint32_t af[2][4], bf[2][4];
            #pragma unroll
            for (int mt = 0; mt < 2; mt++) {
                int lr = mt * 16 + (lane & 15);     // local row in pair tile
                int ku = (lane >> 4) + ku0;
                ldsm4(af[mt], sA + lr * 128 + ((ku ^ (lr & 7)) << 4));
            }
            #pragma unroll
            for (int nh = 0; nh < 2; nh++) {
                int n  = wn * 32 + nh * 16 + (lane & 7) + ((lane >> 4) << 3);
                int ku = ((lane & 8) >> 3) + ku0;
                ldsm4(bf[nh], sB + n * 128 + ((ku ^ (n & 7)) << 4));
            }
            #pragma unroll
            for (int mt = 0; mt < 2; mt++)
                #pragma unroll
                for (int nt = 0; nt < 4; nt++)
                    mma_f16(acc[mt][nt],
                            af[mt][0], af[mt][1], af[mt][2], af[mt][3],
                            bf[nt >> 1][(nt & 1) * 2], bf[nt >> 1][(nt & 1) * 2 + 1]);
        }
    };

    // prime: slab0 chunks 0,1
    prefA(g_Ah + (size_t)mh * 128 * K2, 0);
    prefA(g_Ah + (size_t)mh * 128 * K2, 1);

    for (int t = 0; t < SS; ++t) {
        const __half* Asl = g_Ah + (size_t)t * BB * K2 + (size_t)mh * 128 * K2;

        float acc[2][4][4];
        #pragma unroll
        for (int mt = 0; mt < 2; mt++)
            #pragma unroll
            for (int nt = 0; nt < 4; nt++)
                #pragma unroll
                for (int r = 0; r < 4; r++) acc[mt][nt][r] = 0.f;

        // ---- pre-wait region: mlp chunks 0..3 (pair-local pipeline) ----
        for (int cc = 0; cc < 4; cc++) {
            if (cc < 2) prefA(Asl, cc + 2);
            if      (cc <  2) CP_WAIT(2);
            else if (cc == 2) CP_WAIT(1);
            else              CP_WAIT(0);
            BAR_PAIR();
            do_chunk(cc, acc);
        }

        // ---- global barrier wait (arrive happened at end of previous step) ----
        if (t > 0) {
            if (tid == 0) {
                while (*((volatile unsigned*)&g_gen) == gen) { }
                __threadfence();
            }
            gen += 1u;
        }
        __syncthreads();

        // ---- h chunks 4..19 (pair-local pipeline) ----
        prefA(Asl, 4);
        prefA(Asl, 5);
        for (int cc = 4; cc < NCH; cc++) {
            if (cc + 2 < NCH) prefA(Asl, cc + 2);
            if      (cc <  NCH - 2) CP_WAIT(2);
            else if (cc == NCH - 2) CP_WAIT(1);
            else                    CP_WAIT(0);
            BAR_PAIR();
            do_chunk(cc, acc);
        }
        __syncthreads();   // all pairs done -> stage region reusable as sg

        // ---- epilogue: acc -> sg[col][m] ----
        #pragma unroll
        for (int mt = 0; mt < 2; mt++) {
            int m0 = wm * 32 + mt * 16 + (lane >> 2);
            #pragma unroll
            for (int nt = 0; nt < 4; nt++) {
                int c0 = wn * 32 + nt * 8 + 2 * (lane & 3);
                sg[c0 * 132 + m0]           = acc[mt][nt][0];
                sg[(c0 + 1) * 132 + m0]     = acc[mt][nt][1];
                sg[c0 * 132 + m0 + 8]       = acc[mt][nt][2];
                sg[(c0 + 1) * 132 + m0 + 8] = acc[mt][nt][3];
            }
        }
        __syncthreads();

        // ---- cell update ----
        {
            const int b  = tid & 127;
            const int js = (tid >> 7) * 8;
            const float* bs = sbias[t > 0 ? 1 : 0];
            __align__(16) __half hbuf[8];
            #pragma unroll
            for (int q = 0; q < 8; q++) {
                int jl = js + q;
                float iv = sg[jl * 132 + b]        + bs[jl];
                float fv = sg[(16 + jl) * 132 + b] + bs[16 + jl];
                float gv = sg[(32 + jl) * 132 + b] + bs[32 + jl];
                float ov = sg[(48 + jl) * 132 + b] + bs[48 + jl];
                iv = 1.f / (1.f + expf(-iv));
                fv = 1.f / (1.f + expf(-fv));
                ov = 1.f / (1.f + expf(-ov));
                gv = tanhf(gv);
                int ci = (j0 + jl) * BB + mh * 128 + b;
                float cnew = fmaf(fv, g_c[ci], iv * gv);
                g_c[ci] = cnew;
                hbuf[q] = __float2half(ov * tanhf(cnew));
            }
            __half* hd = g_Ah + (size_t)(t + 1) * BB * K2
                       + (size_t)(mh * 128 + b) * K2 + 256 + j0 + js;
            *(uint4*)hd = *(uint4*)hbuf;
        }
        __syncthreads();   // sg reads done before stages reused

        // ---- split-barrier arrive + prime next-step mlp chunks ----
        if (t + 1 < SS) {
            if (tid == 0) {
                __threadfence();
                unsigned ticket = atomicAdd(&g_cnt, 1u);
                if (ticket == NCTA - 1u) {
                    g_cnt = 0u;
                    __threadfence();
                    atomicAdd(&g_gen, 1u);
                }
            }
            const __half* AslN = Asl + (size_t)BB * K2;
            prefA(AslN, 0);
            prefA(AslN, 1);
        }
    }
    #undef BAR_PAIR
}

// ---------------- kernel 5: out[b][t][a] = h_t @ Wout^T + bout ----------------
__global__ void finalout_kernel(const float* __restrict__ Wout,
                                const float* __restrict__ bout,
                                float* __restrict__ dout)
{
    __shared__ float sH[128 * 33];
    __shared__ float sWT[32 * 68];
    const int tid = threadIdx.x;
    const int tt  = blockIdx.x >> 1;
    const int b0  = (blockIdx.x & 1) * 128;
    const int b   = tid & 127;
    const int ab  = (tid >> 7) * 32;

    const __half* hsl = g_Ah + (size_t)(tt + 1) * BB * K2;

    float acc[32];
    #pragma unroll
    for (int r = 0; r < 32; r++) acc[r] = 0.f;

    for (int jc = 0; jc < 32; jc++) {
        #pragma unroll
        for (int q = 0; q < 16; q++) {
            int idx = q * 256 + tid;
            int row = idx >> 5, j = idx & 31;
            sH[row * 33 + j] = __half2float(hsl[(size_t)(b0 + row) * K2 + 256 + jc * 32 + j]);
        }
        #pragma unroll
        for (int q = 0; q < 8; q++) {
            int idx = q * 256 + tid;
            int a = idx >> 5, j = idx & 31;
            sWT[j * 68 + a] = Wout[a * 1024 + jc * 32 + j];
        }
        __syncthreads();
        #pragma unroll 4
        for (int k = 0; k < 32; k++) {
            float av = sH[b * 33 + k];
            const float4* wp = (const float4*)(sWT + k * 68 + ab);
            #pragma unroll
            for (int r = 0; r < 8; r++) {
                float4 wv = wp[r];
                acc[r*4+0] = fmaf(av, wv.x, acc[r*4+0]);
                acc[r*4+1] = fmaf(av, wv.y, acc[r*4+1]);
                acc[r*4+2] = fmaf(av, wv.z, acc[r*4+2]);
                acc[r*4+3] = fmaf(av, wv.w, acc[r*4+3]);
            }
        }
        __syncthreads();
    }
    float* dp = dout + (size_t)(b0 + b) * SS * AA + tt * AA + ab;
    #pragma unroll
    for (int r = 0; r < 32; r++) dp[r] = acc[r] + bout[ab + r];
}

// ---------------- launch ----------------
extern "C" void kernel_launch(void* const* d_in, const int* in_sizes, int n_in,
                              void* d_out, int out_size)
{
    const float* observe  = (const float*)d_in[0];
    const float* obstacle = (const float*)d_in[1];
    const float* mask     = (const float*)d_in[2];
    const float* W1       = (const float*)d_in[3];
    const float* b1       = (const float*)d_in[4];
    const float* W2       = (const float*)d_in[5];
    const float* b2       = (const float*)d_in[6];
    const float* W_ih     = (const float*)d_in[7];
    const float* b_ih     = (const float*)d_in[8];
    const float* W_hh     = (const float*)d_in[9];
    const float* b_hh     = (const float*)d_in[10];
    const float* W_out    = (const float*)d_in[11];
    const float* b_out    = (const float*)d_in[12];
    float* out = (float*)d_out;

    cudaFuncSetAttribute(lstm_kernel, cudaFuncAttributeMaxDynamicSharedMemorySize, SMEM_BYTES);

    bias_kernel<<<16, 256>>>(W2, b1, b2, b_ih, b_hh, W_ih, b_out);
    collapse_kernel<<<IN_D, 256>>>(W1, W2);
    wprep_kernel<<<64, 256>>>(W_ih, W_hh, W_out);
    mlp_kernel<<<SS * 16, 256>>>(observe, obstacle, mask);
    lstm_kernel<<<NCTA, 256, SMEM_BYTES>>>(0);
    finalout_kernel<<<SS * 2, 256>>>(W_out, b_out, out);
}